// round 1
// baseline (speedup 1.0000x reference)
#include <cuda_runtime.h>
#include <cuda_bf16.h>
#include <math.h>

// ---------------------------------------------------------------------------
// CrossAttention (IP-adapter style), fp32 baseline.
// B=16, N=2048, QUERY_DIM=CONTEXT_DIM=1024, HEADS=16, DIM_HEAD=64,
// ctx len 333 = 77 text + 256 img.
// Pipeline:
//   Q   = x @ Wq                  [32768,1024]
//   K/V = ctx_txt @ Wk/Wv         [1232,1024]
//   Kip/Vip = ctx_img @ Wk_ip/...[4096,1024]
//   A   = attn(Q,K,V) + attn(Q,Kip,Vip)   (independent softmaxes)
//   out = A @ Wo + bo
// ---------------------------------------------------------------------------

#define B_      16
#define N_      2048
#define HEADS_  16
#define DHEAD_  64
#define INNER_  1024
#define CTXL_   333
#define TXT_    77
#define IMG_    256
#define SCALE_  0.125f   // 64^-0.5

// Scratch (static device allocations are the sanctioned workaround).
__device__ float g_Q  [(long long)B_ * N_ * INNER_];
__device__ float g_K  [(long long)B_ * TXT_ * INNER_];
__device__ float g_V  [(long long)B_ * TXT_ * INNER_];
__device__ float g_Kip[(long long)B_ * IMG_ * INNER_];
__device__ float g_Vip[(long long)B_ * IMG_ * INNER_];
__device__ float g_A  [(long long)B_ * N_ * INNER_];

// ---------------------------------------------------------------------------
// Tiled SGEMM: C[M,N] = gatherA[M,K] @ B[K,N] (+bias)
// A rows are gathered: row r -> A + (r/rpb)*bstride + roff + (r%rpb)*K
// BM=BN=128, BK=16, 256 threads, 8x8 per thread.
// ---------------------------------------------------------------------------
#define BM 128
#define BN 128
#define BK 16

__global__ __launch_bounds__(256) void sgemm_kernel(
    const float* __restrict__ A, const float* __restrict__ Bmat,
    const float* __restrict__ bias, float* __restrict__ C,
    int M, int K, int N,
    int rpb, long long bstride, long long roff, int add_bias)
{
    __shared__ float As[BK][BM + 4];   // padded: conflict-free transposed stores
    __shared__ float Bs[BK][BN];

    const int tid = threadIdx.x;
    const int tx  = tid & 15;          // 0..15  (N direction)
    const int ty  = tid >> 4;          // 0..15  (M direction)
    const int m0  = blockIdx.y * BM;
    const int n0  = blockIdx.x * BN;

    // A-tile load mapping: thread -> (row m, float4 col c and c+2)
    const int lm = tid >> 1;           // 0..127
    const int lc = tid & 1;            // 0..1
    const int gm = m0 + lm;
    const float* arow = nullptr;
    if (gm < M) {
        int bidx = gm / rpb;
        int t    = gm - bidx * rpb;
        arow = A + (long long)bidx * bstride + roff + (long long)t * K;
    }
    // B-tile load mapping
    const int kb = tid >> 5;           // 0..7
    const int cb = tid & 31;           // 0..31

    float acc[8][8];
#pragma unroll
    for (int i = 0; i < 8; i++)
#pragma unroll
        for (int j = 0; j < 8; j++) acc[i][j] = 0.f;

    const float4 z4 = make_float4(0.f, 0.f, 0.f, 0.f);

    for (int k0 = 0; k0 < K; k0 += BK) {
        float4 a0 = arow ? *(const float4*)(arow + k0 + lc * 4)       : z4;
        float4 a1 = arow ? *(const float4*)(arow + k0 + lc * 4 + 8)   : z4;
        float4 b0 = *(const float4*)(Bmat + (long long)(k0 + kb)     * N + n0 + cb * 4);
        float4 b1 = *(const float4*)(Bmat + (long long)(k0 + kb + 8) * N + n0 + cb * 4);

        __syncthreads();
        As[lc * 4 + 0][lm] = a0.x;
        As[lc * 4 + 1][lm] = a0.y;
        As[lc * 4 + 2][lm] = a0.z;
        As[lc * 4 + 3][lm] = a0.w;
        As[lc * 4 + 8][lm] = a1.x;
        As[lc * 4 + 9][lm] = a1.y;
        As[lc * 4 + 10][lm] = a1.z;
        As[lc * 4 + 11][lm] = a1.w;
        *(float4*)&Bs[kb][cb * 4]     = b0;
        *(float4*)&Bs[kb + 8][cb * 4] = b1;
        __syncthreads();

#pragma unroll
        for (int k = 0; k < BK; k++) {
            float a[8], b[8];
            float4 av0 = *(const float4*)&As[k][ty * 8];
            float4 av1 = *(const float4*)&As[k][ty * 8 + 4];
            float4 bv0 = *(const float4*)&Bs[k][tx * 8];
            float4 bv1 = *(const float4*)&Bs[k][tx * 8 + 4];
            a[0]=av0.x; a[1]=av0.y; a[2]=av0.z; a[3]=av0.w;
            a[4]=av1.x; a[5]=av1.y; a[6]=av1.z; a[7]=av1.w;
            b[0]=bv0.x; b[1]=bv0.y; b[2]=bv0.z; b[3]=bv0.w;
            b[4]=bv1.x; b[5]=bv1.y; b[6]=bv1.z; b[7]=bv1.w;
#pragma unroll
            for (int i = 0; i < 8; i++)
#pragma unroll
                for (int j = 0; j < 8; j++)
                    acc[i][j] += a[i] * b[j];
        }
    }

#pragma unroll
    for (int i = 0; i < 8; i++) {
        int gm2 = m0 + ty * 8 + i;
        if (gm2 >= M) continue;
        float* crow = C + (long long)gm2 * N + n0 + tx * 8;
#pragma unroll
        for (int j = 0; j < 8; j += 4) {
            float4 v = make_float4(acc[i][j], acc[i][j+1], acc[i][j+2], acc[i][j+3]);
            if (add_bias) {
                const float* brow = bias + n0 + tx * 8 + j;
                v.x += brow[0]; v.y += brow[1]; v.z += brow[2]; v.w += brow[3];
            }
            *(float4*)(crow + j) = v;
        }
    }
}

// ---------------------------------------------------------------------------
// Attention: one thread = one q row (128 rows per CTA), online softmax,
// K/V streamed through SMEM in 128-row chunks.
// Q/K/V layouts: [rows, HEADS*DHEAD] row-major; head h occupies cols h*64..
// grid = (N/128, HEADS, B), block = 128
// ---------------------------------------------------------------------------
#define CHUNK 128

__global__ __launch_bounds__(128, 3) void attn_kernel(
    const float* __restrict__ Q, const float* __restrict__ K,
    const float* __restrict__ V, float* __restrict__ O,
    int L, int accumulate)
{
    __shared__ float4 Ks[CHUNK][16];
    __shared__ float4 Vs[CHUNK][16];

    const int b    = blockIdx.z;
    const int h    = blockIdx.y;
    const int tile = blockIdx.x;
    const int r    = threadIdx.x;

    const long long qrow = (long long)b * N_ + tile * 128 + r;
    const float4* qptr = (const float4*)(Q + qrow * INNER_ + h * DHEAD_);

    float4 q[16];
#pragma unroll
    for (int i = 0; i < 16; i++) q[i] = qptr[i];

    float4 acc[16];
#pragma unroll
    for (int i = 0; i < 16; i++) acc[i] = make_float4(0.f, 0.f, 0.f, 0.f);
    float m = -1e30f;
    float l = 0.f;

    for (int c0 = 0; c0 < L; c0 += CHUNK) {
        const int rows = min(CHUNK, L - c0);
        __syncthreads();
        for (int idx = threadIdx.x; idx < rows * 16; idx += 128) {
            int j  = idx >> 4;
            int d4 = idx & 15;
            long long kr = (long long)b * L + c0 + j;
            Ks[j][d4] = ((const float4*)(K + kr * INNER_ + h * DHEAD_))[d4];
            Vs[j][d4] = ((const float4*)(V + kr * INNER_ + h * DHEAD_))[d4];
        }
        __syncthreads();

        for (int j = 0; j < rows; j++) {
            float s = 0.f;
#pragma unroll
            for (int d = 0; d < 16; d++) {
                float4 kk = Ks[j][d];
                s += q[d].x * kk.x + q[d].y * kk.y + q[d].z * kk.z + q[d].w * kk.w;
            }
            s *= SCALE_;
            if (s > m) {
                float corr = __expf(m - s);
                l *= corr;
#pragma unroll
                for (int d = 0; d < 16; d++) {
                    acc[d].x *= corr; acc[d].y *= corr;
                    acc[d].z *= corr; acc[d].w *= corr;
                }
                m = s;
            }
            float p = __expf(s - m);
            l += p;
#pragma unroll
            for (int d = 0; d < 16; d++) {
                float4 vv = Vs[j][d];
                acc[d].x += p * vv.x; acc[d].y += p * vv.y;
                acc[d].z += p * vv.z; acc[d].w += p * vv.w;
            }
        }
    }

    const float inv = 1.f / l;
    float4* optr = (float4*)(O + qrow * INNER_ + h * DHEAD_);
    if (accumulate) {
#pragma unroll
        for (int i = 0; i < 16; i++) {
            float4 o = optr[i];
            o.x += acc[i].x * inv; o.y += acc[i].y * inv;
            o.z += acc[i].z * inv; o.w += acc[i].w * inv;
            optr[i] = o;
        }
    } else {
#pragma unroll
        for (int i = 0; i < 16; i++) {
            optr[i] = make_float4(acc[i].x * inv, acc[i].y * inv,
                                  acc[i].z * inv, acc[i].w * inv);
        }
    }
}

// ---------------------------------------------------------------------------
extern "C" void kernel_launch(void* const* d_in, const int* in_sizes, int n_in,
                              void* d_out, int out_size)
{
    const float* x     = (const float*)d_in[0];
    const float* ctx   = (const float*)d_in[1];
    const float* Wq    = (const float*)d_in[2];
    const float* Wk    = (const float*)d_in[3];
    const float* Wv    = (const float*)d_in[4];
    const float* Wk_ip = (const float*)d_in[5];
    const float* Wv_ip = (const float*)d_in[6];
    const float* Wo    = (const float*)d_in[7];
    const float* bo    = (const float*)d_in[8];
    float* out = (float*)d_out;

    float *Q, *K, *V, *Kip, *Vip, *A;
    cudaGetSymbolAddress((void**)&Q,   g_Q);
    cudaGetSymbolAddress((void**)&K,   g_K);
    cudaGetSymbolAddress((void**)&V,   g_V);
    cudaGetSymbolAddress((void**)&Kip, g_Kip);
    cudaGetSymbolAddress((void**)&Vip, g_Vip);
    cudaGetSymbolAddress((void**)&A,   g_A);

    const int M_q   = B_ * N_;    // 32768
    const int M_txt = B_ * TXT_;  // 1232
    const int M_img = B_ * IMG_;  // 4096

    // Projections
    sgemm_kernel<<<dim3(INNER_ / BN, (M_q + BM - 1) / BM), 256>>>(
        x, Wq, nullptr, Q, M_q, 1024, INNER_, N_, (long long)N_ * 1024, 0, 0);
    sgemm_kernel<<<dim3(INNER_ / BN, (M_txt + BM - 1) / BM), 256>>>(
        ctx, Wk, nullptr, K, M_txt, 1024, INNER_, TXT_, (long long)CTXL_ * 1024, 0, 0);
    sgemm_kernel<<<dim3(INNER_ / BN, (M_txt + BM - 1) / BM), 256>>>(
        ctx, Wv, nullptr, V, M_txt, 1024, INNER_, TXT_, (long long)CTXL_ * 1024, 0, 0);
    sgemm_kernel<<<dim3(INNER_ / BN, (M_img + BM - 1) / BM), 256>>>(
        ctx, Wk_ip, nullptr, Kip, M_img, 1024, INNER_, IMG_, (long long)CTXL_ * 1024,
        (long long)TXT_ * 1024, 0);
    sgemm_kernel<<<dim3(INNER_ / BN, (M_img + BM - 1) / BM), 256>>>(
        ctx, Wv_ip, nullptr, Vip, M_img, 1024, INNER_, IMG_, (long long)CTXL_ * 1024,
        (long long)TXT_ * 1024, 0);

    // Attention: text writes, img accumulates (IMG_SCALE = 1)
    attn_kernel<<<dim3(N_ / 128, HEADS_, B_), 128>>>(Q, K, V, A, TXT_, 0);
    attn_kernel<<<dim3(N_ / 128, HEADS_, B_), 128>>>(Q, Kip, Vip, A, IMG_, 1);

    // Output projection + bias
    sgemm_kernel<<<dim3(INNER_ / BN, (M_q + BM - 1) / BM), 256>>>(
        A, Wo, bo, out, M_q, 1024, 1024, M_q, 0, 0, 1);
}

// round 4
// speedup vs baseline: 1.5215x; 1.5215x over previous
#include <cuda_runtime.h>
#include <cuda_bf16.h>
#include <math.h>
#include <stdint.h>

// ---------------------------------------------------------------------------
// CrossAttention: mma.sync(bf16x3-split) GEMMs + fp32 flash attention.
// B=16, N=2048, dims 1024, HEADS=16, DHEAD=64, ctx 333 = 77 txt + 256 img.
// NOTE: tcgen05 is unavailable (harness compiles via compute_103 virtual arch),
// so tensor work goes through mma.sync HMMA.
// ---------------------------------------------------------------------------

#define B_      16
#define N_      2048
#define HEADS_  16
#define DHEAD_  64
#define INNER_  1024
#define CTXL_   333
#define TXT_    77
#define IMG_    256
#define SCALE_  0.125f

__device__ float g_Q  [(long long)B_ * N_ * INNER_];
__device__ float g_K  [(long long)B_ * TXT_ * INNER_];
__device__ float g_V  [(long long)B_ * TXT_ * INNER_];
__device__ float g_Kip[(long long)B_ * IMG_ * INNER_];
__device__ float g_Vip[(long long)B_ * IMG_ * INNER_];
__device__ float g_A  [(long long)B_ * N_ * INNER_];

// ---------------------------------------------------------------------------
// helpers
// ---------------------------------------------------------------------------
__device__ __forceinline__ void split2(float x, float y, uint32_t& h, uint32_t& l) {
    __nv_bfloat16 hx = __float2bfloat16(x);
    __nv_bfloat16 hy = __float2bfloat16(y);
    __nv_bfloat16 lx = __float2bfloat16(x - __bfloat162float(hx));
    __nv_bfloat16 ly = __float2bfloat16(y - __bfloat162float(hy));
    h = (uint32_t)__bfloat16_as_ushort(hx) | ((uint32_t)__bfloat16_as_ushort(hy) << 16);
    l = (uint32_t)__bfloat16_as_ushort(lx) | ((uint32_t)__bfloat16_as_ushort(ly) << 16);
}

__device__ __forceinline__ void mma16816(float* c, const uint32_t* a, const uint32_t* b) {
    asm volatile(
        "mma.sync.aligned.m16n8k16.row.col.f32.bf16.bf16.f32 "
        "{%0,%1,%2,%3}, {%4,%5,%6,%7}, {%8,%9}, {%0,%1,%2,%3};"
        : "+f"(c[0]), "+f"(c[1]), "+f"(c[2]), "+f"(c[3])
        : "r"(a[0]), "r"(a[1]), "r"(a[2]), "r"(a[3]), "r"(b[0]), "r"(b[1]));
}

// ---------------------------------------------------------------------------
// mma.sync GEMM: C[M,1024] = gatherA[M,1024] @ W[1024,1024] (+bias)
// CTA 128x128 tile, 8 warps (warp tile 32x64), K chunk 32, bf16x3 split.
// A rows gathered: row r -> A + (r/rpb)*bstride + roff + (r%rpb)*1024
// ---------------------------------------------------------------------------
#define KC    32
#define KPAD  40   // row stride in bf16 elements (20 words -> conflict-free frags)

__global__ __launch_bounds__(256) void gemm_mma(
    const float* __restrict__ A, const float* __restrict__ W,
    const float* __restrict__ bias, float* __restrict__ C,
    int M, int rpb, long long bstride, long long roff, int add_bias)
{
    __shared__ __align__(16) __nv_bfloat16 AsH[128][KPAD];
    __shared__ __align__(16) __nv_bfloat16 AsL[128][KPAD];
    __shared__ __align__(16) __nv_bfloat16 BsH[128][KPAD];  // [n][k] = W^T tile
    __shared__ __align__(16) __nv_bfloat16 BsL[128][KPAD];

    const int tid  = threadIdx.x;
    const int wid  = tid >> 5;
    const int lane = tid & 31;
    const int gid  = lane >> 2;   // 0..7
    const int tig  = lane & 3;    // 0..3
    const int m0   = blockIdx.y * 128;
    const int n0   = blockIdx.x * 128;
    const int mb   = (wid & 3) * 32;   // warp m offset in tile
    const int nb   = (wid >> 2) * 64;  // warp n offset in tile

    // ---- A staging mapping: thread -> (row m = tid/2, k half = tid&1)
    const int am = tid >> 1;
    const int akh = tid & 1;
    const float* arow = nullptr;
    {
        int gm = m0 + am;
        if (gm < M) {
            int bi = gm / rpb;
            int t2 = gm - bi * rpb;
            arow = A + (long long)bi * bstride + roff + (long long)t2 * 1024 + akh * 16;
        }
    }
    // ---- B staging mapping: thread -> (col n = tid&127, k half = tid>>7)
    const int bn  = tid & 127;
    const int bkh = tid >> 7;
    const float* bcol = W + n0 + bn + (long long)bkh * 16 * 1024;

    float acc[2][8][4];
#pragma unroll
    for (int mf = 0; mf < 2; mf++)
#pragma unroll
        for (int nf = 0; nf < 8; nf++)
#pragma unroll
            for (int j = 0; j < 4; j++) acc[mf][nf][j] = 0.f;

    for (int kc = 0; kc < 1024 / KC; kc++) {
        const int k0 = kc * KC;

        // ---- stage A (16 floats per thread: row am, k [akh*16, +16))
        {
            float4 v0, v1, v2, v3;
            if (arow) {
                const float* p = arow + k0;
                v0 = *(const float4*)(p);
                v1 = *(const float4*)(p + 4);
                v2 = *(const float4*)(p + 8);
                v3 = *(const float4*)(p + 12);
            } else {
                v0 = v1 = v2 = v3 = make_float4(0.f, 0.f, 0.f, 0.f);
            }
            uint32_t h0, l0, h1, l1;
            split2(v0.x, v0.y, h0, l0); split2(v0.z, v0.w, h1, l1);
            *(uint2*)&AsH[am][akh * 16 + 0] = make_uint2(h0, h1);
            *(uint2*)&AsL[am][akh * 16 + 0] = make_uint2(l0, l1);
            split2(v1.x, v1.y, h0, l0); split2(v1.z, v1.w, h1, l1);
            *(uint2*)&AsH[am][akh * 16 + 4] = make_uint2(h0, h1);
            *(uint2*)&AsL[am][akh * 16 + 4] = make_uint2(l0, l1);
            split2(v2.x, v2.y, h0, l0); split2(v2.z, v2.w, h1, l1);
            *(uint2*)&AsH[am][akh * 16 + 8] = make_uint2(h0, h1);
            *(uint2*)&AsL[am][akh * 16 + 8] = make_uint2(l0, l1);
            split2(v3.x, v3.y, h0, l0); split2(v3.z, v3.w, h1, l1);
            *(uint2*)&AsH[am][akh * 16 + 12] = make_uint2(h0, h1);
            *(uint2*)&AsL[am][akh * 16 + 12] = make_uint2(l0, l1);
        }
        // ---- stage B^T (16 k values for column bn)
        {
            const float* p = bcol + (long long)k0 * 1024;
#pragma unroll
            for (int i = 0; i < 4; i++) {
                float x0 = p[(4 * i + 0) * 1024];
                float x1 = p[(4 * i + 1) * 1024];
                float x2 = p[(4 * i + 2) * 1024];
                float x3 = p[(4 * i + 3) * 1024];
                uint32_t h0, l0, h1, l1;
                split2(x0, x1, h0, l0); split2(x2, x3, h1, l1);
                *(uint2*)&BsH[bn][bkh * 16 + 4 * i] = make_uint2(h0, h1);
                *(uint2*)&BsL[bn][bkh * 16 + 4 * i] = make_uint2(l0, l1);
            }
        }
        __syncthreads();

        // ---- compute: 2 k-steps of 16
#pragma unroll
        for (int ks = 0; ks < 2; ks++) {
            const int kk = ks * 16 + 2 * tig;
            uint32_t ah[2][4], al[2][4];
#pragma unroll
            for (int mf = 0; mf < 2; mf++) {
                int r = mb + mf * 16;
                ah[mf][0] = *(const uint32_t*)&AsH[r + gid][kk];
                ah[mf][1] = *(const uint32_t*)&AsH[r + gid + 8][kk];
                ah[mf][2] = *(const uint32_t*)&AsH[r + gid][kk + 8];
                ah[mf][3] = *(const uint32_t*)&AsH[r + gid + 8][kk + 8];
                al[mf][0] = *(const uint32_t*)&AsL[r + gid][kk];
                al[mf][1] = *(const uint32_t*)&AsL[r + gid + 8][kk];
                al[mf][2] = *(const uint32_t*)&AsL[r + gid][kk + 8];
                al[mf][3] = *(const uint32_t*)&AsL[r + gid + 8][kk + 8];
            }
#pragma unroll
            for (int nf = 0; nf < 8; nf++) {
                int c = nb + nf * 8 + gid;
                uint32_t bh[2], bl[2];
                bh[0] = *(const uint32_t*)&BsH[c][kk];
                bh[1] = *(const uint32_t*)&BsH[c][kk + 8];
                bl[0] = *(const uint32_t*)&BsL[c][kk];
                bl[1] = *(const uint32_t*)&BsL[c][kk + 8];
#pragma unroll
                for (int mf = 0; mf < 2; mf++) {
                    mma16816(acc[mf][nf], ah[mf], bh);
                    mma16816(acc[mf][nf], al[mf], bh);
                    mma16816(acc[mf][nf], ah[mf], bl);
                }
            }
        }
        __syncthreads();
    }

    // ---- epilogue: c frag (row, col) = (gid [+8], 2*tig [+1])
#pragma unroll
    for (int mf = 0; mf < 2; mf++) {
#pragma unroll
        for (int nf = 0; nf < 8; nf++) {
            int col = n0 + nb + nf * 8 + 2 * tig;
            float b0 = 0.f, b1 = 0.f;
            if (add_bias) { b0 = bias[col]; b1 = bias[col + 1]; }
            int r0 = m0 + mb + mf * 16 + gid;
            int r1 = r0 + 8;
            if (r0 < M) {
                *(float2*)(C + (long long)r0 * 1024 + col) =
                    make_float2(acc[mf][nf][0] + b0, acc[mf][nf][1] + b1);
            }
            if (r1 < M) {
                *(float2*)(C + (long long)r1 * 1024 + col) =
                    make_float2(acc[mf][nf][2] + b0, acc[mf][nf][3] + b1);
            }
        }
    }
}

// ---------------------------------------------------------------------------
// fp32 flash attention (proven in R1): one thread = one q row.
// ---------------------------------------------------------------------------
#define CHUNK 128

__global__ __launch_bounds__(128, 3) void attn_kernel(
    const float* __restrict__ Q, const float* __restrict__ K,
    const float* __restrict__ V, float* __restrict__ O,
    int L, int accumulate)
{
    __shared__ float4 Ks[CHUNK][16];
    __shared__ float4 Vs[CHUNK][16];

    const int b    = blockIdx.z;
    const int h    = blockIdx.y;
    const int tile = blockIdx.x;
    const int r    = threadIdx.x;

    const long long qrow = (long long)b * N_ + tile * 128 + r;
    const float4* qptr = (const float4*)(Q + qrow * INNER_ + h * DHEAD_);

    float4 q[16];
#pragma unroll
    for (int i = 0; i < 16; i++) q[i] = qptr[i];

    float4 acc[16];
#pragma unroll
    for (int i = 0; i < 16; i++) acc[i] = make_float4(0.f, 0.f, 0.f, 0.f);
    float m = -1e30f;
    float l = 0.f;

    for (int c0 = 0; c0 < L; c0 += CHUNK) {
        const int rows = min(CHUNK, L - c0);
        __syncthreads();
        for (int idx = threadIdx.x; idx < rows * 16; idx += 128) {
            int j  = idx >> 4;
            int d4 = idx & 15;
            long long kr = (long long)b * L + c0 + j;
            Ks[j][d4] = ((const float4*)(K + kr * INNER_ + h * DHEAD_))[d4];
            Vs[j][d4] = ((const float4*)(V + kr * INNER_ + h * DHEAD_))[d4];
        }
        __syncthreads();

        for (int j = 0; j < rows; j++) {
            float s = 0.f;
#pragma unroll
            for (int d = 0; d < 16; d++) {
                float4 kk = Ks[j][d];
                s += q[d].x * kk.x + q[d].y * kk.y + q[d].z * kk.z + q[d].w * kk.w;
            }
            s *= SCALE_;
            if (s > m) {
                float corr = __expf(m - s);
                l *= corr;
#pragma unroll
                for (int d = 0; d < 16; d++) {
                    acc[d].x *= corr; acc[d].y *= corr;
                    acc[d].z *= corr; acc[d].w *= corr;
                }
                m = s;
            }
            float p = __expf(s - m);
            l += p;
#pragma unroll
            for (int d = 0; d < 16; d++) {
                float4 vv = Vs[j][d];
                acc[d].x += p * vv.x; acc[d].y += p * vv.y;
                acc[d].z += p * vv.z; acc[d].w += p * vv.w;
            }
        }
    }

    const float inv = 1.f / l;
    float4* optr = (float4*)(O + qrow * INNER_ + h * DHEAD_);
    if (accumulate) {
#pragma unroll
        for (int i = 0; i < 16; i++) {
            float4 o = optr[i];
            o.x += acc[i].x * inv; o.y += acc[i].y * inv;
            o.z += acc[i].z * inv; o.w += acc[i].w * inv;
            optr[i] = o;
        }
    } else {
#pragma unroll
        for (int i = 0; i < 16; i++) {
            optr[i] = make_float4(acc[i].x * inv, acc[i].y * inv,
                                  acc[i].z * inv, acc[i].w * inv);
        }
    }
}

// ---------------------------------------------------------------------------
extern "C" void kernel_launch(void* const* d_in, const int* in_sizes, int n_in,
                              void* d_out, int out_size)
{
    const float* x     = (const float*)d_in[0];
    const float* ctx   = (const float*)d_in[1];
    const float* Wq    = (const float*)d_in[2];
    const float* Wk    = (const float*)d_in[3];
    const float* Wv    = (const float*)d_in[4];
    const float* Wk_ip = (const float*)d_in[5];
    const float* Wv_ip = (const float*)d_in[6];
    const float* Wo    = (const float*)d_in[7];
    const float* bo    = (const float*)d_in[8];
    float* out = (float*)d_out;

    float *Q, *K, *V, *Kip, *Vip, *A;
    cudaGetSymbolAddress((void**)&Q,   g_Q);
    cudaGetSymbolAddress((void**)&K,   g_K);
    cudaGetSymbolAddress((void**)&V,   g_V);
    cudaGetSymbolAddress((void**)&Kip, g_Kip);
    cudaGetSymbolAddress((void**)&Vip, g_Vip);
    cudaGetSymbolAddress((void**)&A,   g_A);

    const int M_q   = B_ * N_;    // 32768
    const int M_txt = B_ * TXT_;  // 1232
    const int M_img = B_ * IMG_;  // 4096

    // Projections (mma.sync, bf16x3 split)
    gemm_mma<<<dim3(8, (M_q + 127) / 128), 256>>>(
        x, Wq, nullptr, Q, M_q, N_, (long long)N_ * 1024, 0, 0);
    gemm_mma<<<dim3(8, (M_txt + 127) / 128), 256>>>(
        ctx, Wk, nullptr, K, M_txt, TXT_, (long long)CTXL_ * 1024, 0, 0);
    gemm_mma<<<dim3(8, (M_txt + 127) / 128), 256>>>(
        ctx, Wv, nullptr, V, M_txt, TXT_, (long long)CTXL_ * 1024, 0, 0);
    gemm_mma<<<dim3(8, (M_img + 127) / 128), 256>>>(
        ctx, Wk_ip, nullptr, Kip, M_img, IMG_, (long long)CTXL_ * 1024,
        (long long)TXT_ * 1024, 0);
    gemm_mma<<<dim3(8, (M_img + 127) / 128), 256>>>(
        ctx, Wv_ip, nullptr, Vip, M_img, IMG_, (long long)CTXL_ * 1024,
        (long long)TXT_ * 1024, 0);

    // Attention: text writes, img accumulates (IMG_SCALE = 1)
    attn_kernel<<<dim3(N_ / 128, HEADS_, B_), 128>>>(Q, K, V, A, TXT_, 0);
    attn_kernel<<<dim3(N_ / 128, HEADS_, B_), 128>>>(Q, Kip, Vip, A, IMG_, 1);

    // Output projection + bias
    gemm_mma<<<dim3(8, (M_q + 127) / 128), 256>>>(
        A, Wo, bo, out, M_q, M_q, 0, 0, 1);
}

// round 5
// speedup vs baseline: 1.8303x; 1.2029x over previous
#include <cuda_runtime.h>
#include <cuda_bf16.h>
#include <math.h>
#include <stdint.h>

// ---------------------------------------------------------------------------
// CrossAttention: bf16x3-split mma.sync GEMMs + mma.sync flash attention.
// B=16, N=2048, dims 1024, HEADS=16, DHEAD=64, ctx 333 = 77 txt + 256 img.
// ---------------------------------------------------------------------------

#define B_      16
#define N_      2048
#define HEADS_  16
#define DHEAD_  64
#define INNER_  1024
#define CTXL_   333
#define TXT_    77
#define IMG_    256
#define SCALE_  0.125f

#define NX      (33554432LL)            // 32768*1024
#define NCTX    (16LL * 333 * 1024)

// bf16 hi/lo scratch
__device__ __nv_bfloat16 g_xh[NX],  g_xl[NX];
__device__ __nv_bfloat16 g_ch[NCTX], g_cl[NCTX];
__device__ __nv_bfloat16 g_Wth[6 * 1048576], g_Wtl[6 * 1048576];
__device__ __nv_bfloat16 g_Qh[NX],  g_Ql[NX];
__device__ __nv_bfloat16 g_Kth[1261568], g_Ktl[1261568];
__device__ __nv_bfloat16 g_Vth[1261568], g_Vtl[1261568];
__device__ __nv_bfloat16 g_Kih[4194304], g_Kil[4194304];
__device__ __nv_bfloat16 g_Vih[4194304], g_Vil[4194304];
__device__ __nv_bfloat16 g_Ah[NX],  g_Al[NX];
__device__ float g_O0[NX];
__device__ float g_O1[NX];

// ---------------------------------------------------------------------------
// helpers
// ---------------------------------------------------------------------------
__device__ __forceinline__ void split2(float x, float y, uint32_t& h, uint32_t& l) {
    __nv_bfloat16 hx = __float2bfloat16(x);
    __nv_bfloat16 hy = __float2bfloat16(y);
    __nv_bfloat16 lx = __float2bfloat16(x - __bfloat162float(hx));
    __nv_bfloat16 ly = __float2bfloat16(y - __bfloat162float(hy));
    h = (uint32_t)__bfloat16_as_ushort(hx) | ((uint32_t)__bfloat16_as_ushort(hy) << 16);
    l = (uint32_t)__bfloat16_as_ushort(lx) | ((uint32_t)__bfloat16_as_ushort(ly) << 16);
}

__device__ __forceinline__ void mma16816(float* c, const uint32_t* a, const uint32_t* b) {
    asm volatile(
        "mma.sync.aligned.m16n8k16.row.col.f32.bf16.bf16.f32 "
        "{%0,%1,%2,%3}, {%4,%5,%6,%7}, {%8,%9}, {%0,%1,%2,%3};"
        : "+f"(c[0]), "+f"(c[1]), "+f"(c[2]), "+f"(c[3])
        : "r"(a[0]), "r"(a[1]), "r"(a[2]), "r"(a[3]), "r"(b[0]), "r"(b[1]));
}

// ---------------------------------------------------------------------------
// Pre-convert kernels
// ---------------------------------------------------------------------------
__global__ void conv_split(const float* __restrict__ src,
                           uint32_t* __restrict__ h, uint32_t* __restrict__ l,
                           long long npairs)
{
    long long i = blockIdx.x * (long long)blockDim.x + threadIdx.x;
    long long stride = (long long)gridDim.x * blockDim.x;
    for (; i < npairs; i += stride) {
        float2 v = ((const float2*)src)[i];
        uint32_t hh, ll;
        split2(v.x, v.y, hh, ll);
        h[i] = hh; l[i] = ll;
    }
}

// W[1024 k][1024 n] -> T[n][k] bf16 hi/lo
__global__ void transpose_split(const float* __restrict__ W,
                                __nv_bfloat16* __restrict__ Th,
                                __nv_bfloat16* __restrict__ Tl)
{
    __shared__ float ts[32][33];
    const int n0 = blockIdx.x * 32, k0 = blockIdx.y * 32;
    const int tx = threadIdx.x, ty = threadIdx.y;
#pragma unroll
    for (int i = 0; i < 4; i++)
        ts[ty + 8 * i][tx] = W[(long long)(k0 + ty + 8 * i) * 1024 + n0 + tx];
    __syncthreads();
#pragma unroll
    for (int i = 0; i < 4; i++) {
        float v = ts[tx][ty + 8 * i];   // W[k0+tx][n0+ty+8i]
        __nv_bfloat16 h = __float2bfloat16(v);
        __nv_bfloat16 l = __float2bfloat16(v - __bfloat162float(h));
        long long o = (long long)(n0 + ty + 8 * i) * 1024 + k0 + tx;
        Th[o] = h; Tl[o] = l;
    }
}

// merge O0+O1 -> bf16 hi/lo
__global__ void merge_split(const float* __restrict__ O0, const float* __restrict__ O1,
                            uint32_t* __restrict__ h, uint32_t* __restrict__ l,
                            long long npairs)
{
    long long i = blockIdx.x * (long long)blockDim.x + threadIdx.x;
    long long stride = (long long)gridDim.x * blockDim.x;
    for (; i < npairs; i += stride) {
        float2 a = ((const float2*)O0)[i];
        float2 b = ((const float2*)O1)[i];
        uint32_t hh, ll;
        split2(a.x + b.x, a.y + b.y, hh, ll);
        h[i] = hh; l[i] = ll;
    }
}

// ---------------------------------------------------------------------------
// mma.sync GEMM, bf16 hi/lo inputs: C[M,1024] = gatherA[M,1024] @ Wt^T (+bias)
// Wt is [n][k] bf16. CTA 128x128 tile, 8 warps, K chunk 32, 3-term split.
// mode 0: write Ch/Cl bf16 hi/lo.  mode 1: write fp32 C with bias.
// ---------------------------------------------------------------------------
#define KC    32
#define KPAD  40

__global__ __launch_bounds__(256) void gemm_bf16(
    const __nv_bfloat16* __restrict__ Ah, const __nv_bfloat16* __restrict__ Al,
    const __nv_bfloat16* __restrict__ Bh, const __nv_bfloat16* __restrict__ Bl,
    const float* __restrict__ bias, float* __restrict__ Cf,
    __nv_bfloat16* __restrict__ Ch, __nv_bfloat16* __restrict__ Cl,
    int M, int rpb, long long bstride, long long roff, int mode)
{
    __shared__ __align__(16) __nv_bfloat16 AsH[128][KPAD];
    __shared__ __align__(16) __nv_bfloat16 AsL[128][KPAD];
    __shared__ __align__(16) __nv_bfloat16 BsH[128][KPAD];
    __shared__ __align__(16) __nv_bfloat16 BsL[128][KPAD];

    const int tid  = threadIdx.x;
    const int wid  = tid >> 5;
    const int lane = tid & 31;
    const int gid  = lane >> 2;
    const int tig  = lane & 3;
    const int m0   = blockIdx.y * 128;
    const int n0   = blockIdx.x * 128;
    const int mb   = (wid & 3) * 32;
    const int nb   = (wid >> 2) * 64;

    // A staging: thread -> (row tid>>1, k-quarter tid&1 covering 16 elems)
    const int am = tid >> 1;
    const int akq = (tid & 1) * 16;
    const __nv_bfloat16 *arh = nullptr, *arl = nullptr;
    {
        int gm = m0 + am;
        if (gm < M) {
            int bi = gm / rpb;
            int t2 = gm - bi * rpb;
            long long off = (long long)bi * bstride + roff + (long long)t2 * 1024 + akq;
            arh = Ah + off; arl = Al + off;
        }
    }
    // B staging: thread -> (row n = tid&127, k half tid>>7)
    const int bn  = tid & 127;
    const int bkq = (tid >> 7) * 16;
    const __nv_bfloat16* brh = Bh + (long long)(n0 + bn) * 1024 + bkq;
    const __nv_bfloat16* brl = Bl + (long long)(n0 + bn) * 1024 + bkq;

    float acc[2][8][4];
#pragma unroll
    for (int mf = 0; mf < 2; mf++)
#pragma unroll
        for (int nf = 0; nf < 8; nf++)
#pragma unroll
            for (int j = 0; j < 4; j++) acc[mf][nf][j] = 0.f;

    const uint4 z4 = make_uint4(0, 0, 0, 0);

    for (int kc = 0; kc < 1024 / KC; kc++) {
        const int k0 = kc * KC;
        uint4 ah0, ah1, al0, al1;
        if (arh) {
            ah0 = *(const uint4*)(arh + k0);
            ah1 = *(const uint4*)(arh + k0 + 8);
            al0 = *(const uint4*)(arl + k0);
            al1 = *(const uint4*)(arl + k0 + 8);
        } else { ah0 = ah1 = al0 = al1 = z4; }
        uint4 bh0 = *(const uint4*)(brh + k0);
        uint4 bh1 = *(const uint4*)(brh + k0 + 8);
        uint4 bl0 = *(const uint4*)(brl + k0);
        uint4 bl1 = *(const uint4*)(brl + k0 + 8);

        *(uint4*)&AsH[am][akq]     = ah0;
        *(uint4*)&AsH[am][akq + 8] = ah1;
        *(uint4*)&AsL[am][akq]     = al0;
        *(uint4*)&AsL[am][akq + 8] = al1;
        *(uint4*)&BsH[bn][bkq]     = bh0;
        *(uint4*)&BsH[bn][bkq + 8] = bh1;
        *(uint4*)&BsL[bn][bkq]     = bl0;
        *(uint4*)&BsL[bn][bkq + 8] = bl1;
        __syncthreads();

#pragma unroll
        for (int ks = 0; ks < 2; ks++) {
            const int kk = ks * 16 + 2 * tig;
            uint32_t fah[2][4], fal[2][4];
#pragma unroll
            for (int mf = 0; mf < 2; mf++) {
                int r = mb + mf * 16;
                fah[mf][0] = *(const uint32_t*)&AsH[r + gid][kk];
                fah[mf][1] = *(const uint32_t*)&AsH[r + gid + 8][kk];
                fah[mf][2] = *(const uint32_t*)&AsH[r + gid][kk + 8];
                fah[mf][3] = *(const uint32_t*)&AsH[r + gid + 8][kk + 8];
                fal[mf][0] = *(const uint32_t*)&AsL[r + gid][kk];
                fal[mf][1] = *(const uint32_t*)&AsL[r + gid + 8][kk];
                fal[mf][2] = *(const uint32_t*)&AsL[r + gid][kk + 8];
                fal[mf][3] = *(const uint32_t*)&AsL[r + gid + 8][kk + 8];
            }
#pragma unroll
            for (int nf = 0; nf < 8; nf++) {
                int c = nb + nf * 8 + gid;
                uint32_t fbh[2], fbl[2];
                fbh[0] = *(const uint32_t*)&BsH[c][kk];
                fbh[1] = *(const uint32_t*)&BsH[c][kk + 8];
                fbl[0] = *(const uint32_t*)&BsL[c][kk];
                fbl[1] = *(const uint32_t*)&BsL[c][kk + 8];
#pragma unroll
                for (int mf = 0; mf < 2; mf++) {
                    mma16816(acc[mf][nf], fah[mf], fbh);
                    mma16816(acc[mf][nf], fal[mf], fbh);
                    mma16816(acc[mf][nf], fah[mf], fbl);
                }
            }
        }
        __syncthreads();
    }

#pragma unroll
    for (int mf = 0; mf < 2; mf++) {
#pragma unroll
        for (int nf = 0; nf < 8; nf++) {
            int col = n0 + nb + nf * 8 + 2 * tig;
            int r0 = m0 + mb + mf * 16 + gid;
            int r1 = r0 + 8;
            if (mode == 1) {
                float b0 = bias[col], b1 = bias[col + 1];
                if (r0 < M)
                    *(float2*)(Cf + (long long)r0 * 1024 + col) =
                        make_float2(acc[mf][nf][0] + b0, acc[mf][nf][1] + b1);
                if (r1 < M)
                    *(float2*)(Cf + (long long)r1 * 1024 + col) =
                        make_float2(acc[mf][nf][2] + b0, acc[mf][nf][3] + b1);
            } else {
                uint32_t h, l;
                if (r0 < M) {
                    split2(acc[mf][nf][0], acc[mf][nf][1], h, l);
                    *(uint32_t*)(Ch + (long long)r0 * 1024 + col) = h;
                    *(uint32_t*)(Cl + (long long)r0 * 1024 + col) = l;
                }
                if (r1 < M) {
                    split2(acc[mf][nf][2], acc[mf][nf][3], h, l);
                    *(uint32_t*)(Ch + (long long)r1 * 1024 + col) = h;
                    *(uint32_t*)(Cl + (long long)r1 * 1024 + col) = l;
                }
            }
        }
    }
}

// ---------------------------------------------------------------------------
// mma.sync flash attention. CTA = 64 q rows x 1 head, 4 warps (16 rows each).
// KV chunks of 64; S = Q K^T (3-term split), frag softmax, O += P V (3-term).
// Output: fp32 phase buffer (normalized), merged later.
// ---------------------------------------------------------------------------
#define APAD 72

__global__ __launch_bounds__(128, 3) void attn_mma(
    const __nv_bfloat16* __restrict__ Qh, const __nv_bfloat16* __restrict__ Ql,
    const __nv_bfloat16* __restrict__ Kh, const __nv_bfloat16* __restrict__ Kl,
    const __nv_bfloat16* __restrict__ Vh, const __nv_bfloat16* __restrict__ Vl,
    float* __restrict__ O, int L)
{
    extern __shared__ __nv_bfloat16 sm[];
    __nv_bfloat16 (*QsH)[APAD] = (__nv_bfloat16(*)[APAD])(sm);
    __nv_bfloat16 (*QsL)[APAD] = (__nv_bfloat16(*)[APAD])(sm + 64 * APAD);
    __nv_bfloat16 (*KsH)[APAD] = (__nv_bfloat16(*)[APAD])(sm + 2 * 64 * APAD);
    __nv_bfloat16 (*KsL)[APAD] = (__nv_bfloat16(*)[APAD])(sm + 3 * 64 * APAD);
    __nv_bfloat16 (*VtH)[APAD] = (__nv_bfloat16(*)[APAD])(sm + 4 * 64 * APAD);
    __nv_bfloat16 (*VtL)[APAD] = (__nv_bfloat16(*)[APAD])(sm + 5 * 64 * APAD);

    const int tid  = threadIdx.x;
    const int wid  = tid >> 5;
    const int lane = tid & 31;
    const int gid  = lane >> 2;
    const int tig  = lane & 3;
    const int q0   = blockIdx.x * 64;
    const int h    = blockIdx.y;
    const int b    = blockIdx.z;
    const int wr   = wid * 16;          // warp's q-row base in tile

    // ---- stage Q (once): thread -> row tid>>1, col-half (tid&1)*32
    {
        int r = tid >> 1, ch = (tid & 1) * 32;
        long long off = (long long)(b * N_ + q0 + r) * INNER_ + h * DHEAD_ + ch;
#pragma unroll
        for (int u = 0; u < 4; u++) {
            *(uint4*)&QsH[r][ch + 8 * u] = *(const uint4*)(Qh + off + 8 * u);
            *(uint4*)&QsL[r][ch + 8 * u] = *(const uint4*)(Ql + off + 8 * u);
        }
    }

    float acc[8][4];
#pragma unroll
    for (int nf = 0; nf < 8; nf++)
#pragma unroll
        for (int j = 0; j < 4; j++) acc[nf][j] = 0.f;
    float m0 = -1e30f, m1 = -1e30f, l0 = 0.f, l1 = 0.f;

    const uint4 z4 = make_uint4(0, 0, 0, 0);

    for (int c0 = 0; c0 < L; c0 += 64) {
        // ---- stage K chunk + V^T chunk
        __syncthreads();
        {
            int r = tid >> 1, ch = (tid & 1) * 32;
            long long off = (long long)(b * L + c0 + r) * INNER_ + h * DHEAD_ + ch;
            bool ok = (c0 + r) < L;
#pragma unroll
            for (int u = 0; u < 4; u++) {
                uint4 vh = ok ? *(const uint4*)(Kh + off + 8 * u) : z4;
                uint4 vl = ok ? *(const uint4*)(Kl + off + 8 * u) : z4;
                *(uint4*)&KsH[r][ch + 8 * u] = vh;
                *(uint4*)&KsL[r][ch + 8 * u] = vl;
            }
            // V: load row j coalesced, scatter transposed
            int j = tid >> 1, dh = (tid & 1) * 32;
            long long voff = (long long)(b * L + c0 + j) * INNER_ + h * DHEAD_ + dh;
            bool vok = (c0 + j) < L;
#pragma unroll
            for (int u = 0; u < 4; u++) {
                uint4 vh = vok ? *(const uint4*)(Vh + voff + 8 * u) : z4;
                uint4 vl = vok ? *(const uint4*)(Vl + voff + 8 * u) : z4;
                const __nv_bfloat16* eh = (const __nv_bfloat16*)&vh;
                const __nv_bfloat16* el = (const __nv_bfloat16*)&vl;
#pragma unroll
                for (int d = 0; d < 8; d++) {
                    VtH[dh + 8 * u + d][j] = eh[d];
                    VtL[dh + 8 * u + d][j] = el[d];
                }
            }
        }
        __syncthreads();

        // ---- S = Q K^T
        float s[8][4];
#pragma unroll
        for (int nf = 0; nf < 8; nf++)
#pragma unroll
            for (int j = 0; j < 4; j++) s[nf][j] = 0.f;
#pragma unroll
        for (int kf = 0; kf < 4; kf++) {
            const int kk = kf * 16 + 2 * tig;
            uint32_t qah[4], qal[4];
            qah[0] = *(const uint32_t*)&QsH[wr + gid][kk];
            qah[1] = *(const uint32_t*)&QsH[wr + gid + 8][kk];
            qah[2] = *(const uint32_t*)&QsH[wr + gid][kk + 8];
            qah[3] = *(const uint32_t*)&QsH[wr + gid + 8][kk + 8];
            qal[0] = *(const uint32_t*)&QsL[wr + gid][kk];
            qal[1] = *(const uint32_t*)&QsL[wr + gid + 8][kk];
            qal[2] = *(const uint32_t*)&QsL[wr + gid][kk + 8];
            qal[3] = *(const uint32_t*)&QsL[wr + gid + 8][kk + 8];
#pragma unroll
            for (int nf = 0; nf < 8; nf++) {
                int c = nf * 8 + gid;
                uint32_t kb[2], klo[2];
                kb[0]  = *(const uint32_t*)&KsH[c][kk];
                kb[1]  = *(const uint32_t*)&KsH[c][kk + 8];
                klo[0] = *(const uint32_t*)&KsL[c][kk];
                klo[1] = *(const uint32_t*)&KsL[c][kk + 8];
                mma16816(s[nf], qah, kb);
                mma16816(s[nf], qal, kb);
                mma16816(s[nf], qah, klo);
            }
        }

        // ---- scale + mask
#pragma unroll
        for (int nf = 0; nf < 8; nf++) {
            int col = c0 + nf * 8 + 2 * tig;
            s[nf][0] *= SCALE_; s[nf][1] *= SCALE_;
            s[nf][2] *= SCALE_; s[nf][3] *= SCALE_;
            if (col >= L)     { s[nf][0] = -1e30f; s[nf][2] = -1e30f; }
            if (col + 1 >= L) { s[nf][1] = -1e30f; s[nf][3] = -1e30f; }
        }

        // ---- row max (rows gid -> m0, gid+8 -> m1), quad reduce
        float mx0 = -1e30f, mx1 = -1e30f;
#pragma unroll
        for (int nf = 0; nf < 8; nf++) {
            mx0 = fmaxf(mx0, fmaxf(s[nf][0], s[nf][1]));
            mx1 = fmaxf(mx1, fmaxf(s[nf][2], s[nf][3]));
        }
        mx0 = fmaxf(mx0, __shfl_xor_sync(0xffffffff, mx0, 1));
        mx0 = fmaxf(mx0, __shfl_xor_sync(0xffffffff, mx0, 2));
        mx1 = fmaxf(mx1, __shfl_xor_sync(0xffffffff, mx1, 1));
        mx1 = fmaxf(mx1, __shfl_xor_sync(0xffffffff, mx1, 2));

        float nm0 = fmaxf(m0, mx0), nm1 = fmaxf(m1, mx1);
        float corr0 = __expf(m0 - nm0), corr1 = __expf(m1 - nm1);
        m0 = nm0; m1 = nm1;
#pragma unroll
        for (int nf = 0; nf < 8; nf++) {
            acc[nf][0] *= corr0; acc[nf][1] *= corr0;
            acc[nf][2] *= corr1; acc[nf][3] *= corr1;
        }

        // ---- p = exp(s - m), pack bf16 hi/lo, accumulate row sums
        uint32_t ph[8][2], pl[8][2];
        float sum0 = 0.f, sum1 = 0.f;
#pragma unroll
        for (int nf = 0; nf < 8; nf++) {
            float p0 = __expf(s[nf][0] - m0);
            float p1 = __expf(s[nf][1] - m0);
            float p2 = __expf(s[nf][2] - m1);
            float p3 = __expf(s[nf][3] - m1);
            sum0 += p0 + p1; sum1 += p2 + p3;
            split2(p0, p1, ph[nf][0], pl[nf][0]);
            split2(p2, p3, ph[nf][1], pl[nf][1]);
        }
        sum0 += __shfl_xor_sync(0xffffffff, sum0, 1);
        sum0 += __shfl_xor_sync(0xffffffff, sum0, 2);
        sum1 += __shfl_xor_sync(0xffffffff, sum1, 1);
        sum1 += __shfl_xor_sync(0xffffffff, sum1, 2);
        l0 = l0 * corr0 + sum0;
        l1 = l1 * corr1 + sum1;

        // ---- O += P V
#pragma unroll
        for (int kf = 0; kf < 4; kf++) {
            const int kk = kf * 16 + 2 * tig;
            uint32_t pah[4] = { ph[2*kf][0], ph[2*kf][1], ph[2*kf+1][0], ph[2*kf+1][1] };
            uint32_t pal[4] = { pl[2*kf][0], pl[2*kf][1], pl[2*kf+1][0], pl[2*kf+1][1] };
#pragma unroll
            for (int nfo = 0; nfo < 8; nfo++) {
                int c = nfo * 8 + gid;
                uint32_t vb[2], vlo[2];
                vb[0]  = *(const uint32_t*)&VtH[c][kk];
                vb[1]  = *(const uint32_t*)&VtH[c][kk + 8];
                vlo[0] = *(const uint32_t*)&VtL[c][kk];
                vlo[1] = *(const uint32_t*)&VtL[c][kk + 8];
                mma16816(acc[nfo], pah, vb);
                mma16816(acc[nfo], pal, vb);
                mma16816(acc[nfo], pah, vlo);
            }
        }
    }

    // ---- epilogue: normalized fp32 output
    const float inv0 = 1.f / l0, inv1 = 1.f / l1;
    const long long r0 = (long long)(b * N_ + q0 + wr + gid);
    const long long r1 = r0 + 8;
#pragma unroll
    for (int nfo = 0; nfo < 8; nfo++) {
        int col = h * DHEAD_ + nfo * 8 + 2 * tig;
        *(float2*)(O + r0 * INNER_ + col) =
            make_float2(acc[nfo][0] * inv0, acc[nfo][1] * inv0);
        *(float2*)(O + r1 * INNER_ + col) =
            make_float2(acc[nfo][2] * inv1, acc[nfo][3] * inv1);
    }
}

// ---------------------------------------------------------------------------
extern "C" void kernel_launch(void* const* d_in, const int* in_sizes, int n_in,
                              void* d_out, int out_size)
{
    const float* x     = (const float*)d_in[0];
    const float* ctx   = (const float*)d_in[1];
    const float* Ws[6] = { (const float*)d_in[2], (const float*)d_in[3],
                           (const float*)d_in[4], (const float*)d_in[5],
                           (const float*)d_in[6], (const float*)d_in[7] };
    const float* bo    = (const float*)d_in[8];
    float* out = (float*)d_out;

    __nv_bfloat16 *xh, *xl, *ch, *cl, *Wth, *Wtl, *Qh, *Ql;
    __nv_bfloat16 *Kth, *Ktl, *Vth, *Vtl, *Kih, *Kil, *Vih, *Vil, *Ah, *Al;
    float *O0, *O1;
    cudaGetSymbolAddress((void**)&xh, g_xh);   cudaGetSymbolAddress((void**)&xl, g_xl);
    cudaGetSymbolAddress((void**)&ch, g_ch);   cudaGetSymbolAddress((void**)&cl, g_cl);
    cudaGetSymbolAddress((void**)&Wth, g_Wth); cudaGetSymbolAddress((void**)&Wtl, g_Wtl);
    cudaGetSymbolAddress((void**)&Qh, g_Qh);   cudaGetSymbolAddress((void**)&Ql, g_Ql);
    cudaGetSymbolAddress((void**)&Kth, g_Kth); cudaGetSymbolAddress((void**)&Ktl, g_Ktl);
    cudaGetSymbolAddress((void**)&Vth, g_Vth); cudaGetSymbolAddress((void**)&Vtl, g_Vtl);
    cudaGetSymbolAddress((void**)&Kih, g_Kih); cudaGetSymbolAddress((void**)&Kil, g_Kil);
    cudaGetSymbolAddress((void**)&Vih, g_Vih); cudaGetSymbolAddress((void**)&Vil, g_Vil);
    cudaGetSymbolAddress((void**)&Ah, g_Ah);   cudaGetSymbolAddress((void**)&Al, g_Al);
    cudaGetSymbolAddress((void**)&O0, g_O0);   cudaGetSymbolAddress((void**)&O1, g_O1);

    static int attr_done = 0;
    if (!attr_done) {
        cudaFuncSetAttribute(attn_mma, cudaFuncAttributeMaxDynamicSharedMemorySize,
                             6 * 64 * APAD * 2);
        attr_done = 1;
    }

    const int M_q   = B_ * N_;    // 32768
    const int M_txt = B_ * TXT_;  // 1232
    const int M_img = B_ * IMG_;  // 4096

    // 1. pre-convert inputs
    conv_split<<<2048, 256>>>(x,   (uint32_t*)xh, (uint32_t*)xl, NX / 2);
    conv_split<<<1024, 256>>>(ctx, (uint32_t*)ch, (uint32_t*)cl, NCTX / 2);
    for (int w = 0; w < 6; w++)
        transpose_split<<<dim3(32, 32), dim3(32, 8)>>>(
            Ws[w], Wth + (long long)w * 1048576, Wtl + (long long)w * 1048576);

    // 2. projections (bf16 hi/lo out)
    gemm_bf16<<<dim3(8, 256), 256>>>(xh, xl, Wth + 0, Wtl + 0, nullptr, nullptr,
        Qh, Ql, M_q, N_, (long long)N_ * 1024, 0, 0);
    gemm_bf16<<<dim3(8, 10), 256>>>(ch, cl, Wth + 1048576, Wtl + 1048576, nullptr, nullptr,
        Kth, Ktl, M_txt, TXT_, (long long)CTXL_ * 1024, 0, 0);
    gemm_bf16<<<dim3(8, 10), 256>>>(ch, cl, Wth + 2 * 1048576, Wtl + 2 * 1048576, nullptr, nullptr,
        Vth, Vtl, M_txt, TXT_, (long long)CTXL_ * 1024, 0, 0);
    gemm_bf16<<<dim3(8, 32), 256>>>(ch, cl, Wth + 3 * 1048576, Wtl + 3 * 1048576, nullptr, nullptr,
        Kih, Kil, M_img, IMG_, (long long)CTXL_ * 1024, (long long)TXT_ * 1024, 0);
    gemm_bf16<<<dim3(8, 32), 256>>>(ch, cl, Wth + 4 * 1048576, Wtl + 4 * 1048576, nullptr, nullptr,
        Vih, Vil, M_img, IMG_, (long long)CTXL_ * 1024, (long long)TXT_ * 1024, 0);

    // 3. attention (two phases into separate fp32 buffers)
    attn_mma<<<dim3(N_ / 64, HEADS_, B_), 128, 6 * 64 * APAD * 2>>>(
        Qh, Ql, Kth, Ktl, Vth, Vtl, O0, TXT_);
    attn_mma<<<dim3(N_ / 64, HEADS_, B_), 128, 6 * 64 * APAD * 2>>>(
        Qh, Ql, Kih, Kil, Vih, Vil, O1, IMG_);

    // 4. merge + split for O-projection
    merge_split<<<2048, 256>>>(O0, O1, (uint32_t*)Ah, (uint32_t*)Al, NX / 2);

    // 5. output projection (fp32 + bias)
    gemm_bf16<<<dim3(8, 256), 256>>>(Ah, Al, Wth + 5 * 1048576, Wtl + 5 * 1048576,
        bo, out, nullptr, nullptr, M_q, M_q, 0, 0, 1);
}

// round 8
// speedup vs baseline: 2.0205x; 1.1039x over previous
#include <cuda_runtime.h>
#include <cuda_bf16.h>
#include <math.h>
#include <stdint.h>

// ---------------------------------------------------------------------------
// CrossAttention: bf16x3-split mma.sync GEMMs (cp.async + ldmatrix pipelined)
// + fused two-phase mma.sync flash attention.
// ---------------------------------------------------------------------------

#define B_      16
#define N_      2048
#define HEADS_  16
#define DHEAD_  64
#define INNER_  1024
#define CTXL_   333
#define TXT_    77
#define IMG_    256
#define SCALE_  0.125f

#define NX      (33554432LL)
#define NCTX    (16LL * 333 * 1024)

__device__ __nv_bfloat16 g_xh[NX],  g_xl[NX];
__device__ __nv_bfloat16 g_ch[NCTX], g_cl[NCTX];
__device__ __nv_bfloat16 g_Wth[6 * 1048576], g_Wtl[6 * 1048576];
__device__ __nv_bfloat16 g_Qh[NX],  g_Ql[NX];
__device__ __nv_bfloat16 g_Kth[1261568], g_Ktl[1261568];
__device__ __nv_bfloat16 g_Vth[1261568], g_Vtl[1261568];
__device__ __nv_bfloat16 g_Kih[4194304], g_Kil[4194304];
__device__ __nv_bfloat16 g_Vih[4194304], g_Vil[4194304];
__device__ __nv_bfloat16 g_Ah[NX],  g_Al[NX];

// ---------------------------------------------------------------------------
__device__ __forceinline__ uint32_t smem_u32(const void* p) {
    uint32_t a;
    asm("{ .reg .u64 t; cvta.to.shared.u64 t, %1; cvt.u32.u64 %0, t; }"
        : "=r"(a) : "l"(p));
    return a;
}

__device__ __forceinline__ void split2(float x, float y, uint32_t& h, uint32_t& l) {
    __nv_bfloat16 hx = __float2bfloat16(x);
    __nv_bfloat16 hy = __float2bfloat16(y);
    __nv_bfloat16 lx = __float2bfloat16(x - __bfloat162float(hx));
    __nv_bfloat16 ly = __float2bfloat16(y - __bfloat162float(hy));
    h = (uint32_t)__bfloat16_as_ushort(hx) | ((uint32_t)__bfloat16_as_ushort(hy) << 16);
    l = (uint32_t)__bfloat16_as_ushort(lx) | ((uint32_t)__bfloat16_as_ushort(ly) << 16);
}

__device__ __forceinline__ void mma16816(float* c, const uint32_t* a, const uint32_t* b) {
    asm volatile(
        "mma.sync.aligned.m16n8k16.row.col.f32.bf16.bf16.f32 "
        "{%0,%1,%2,%3}, {%4,%5,%6,%7}, {%8,%9}, {%0,%1,%2,%3};"
        : "+f"(c[0]), "+f"(c[1]), "+f"(c[2]), "+f"(c[3])
        : "r"(a[0]), "r"(a[1]), "r"(a[2]), "r"(a[3]), "r"(b[0]), "r"(b[1]));
}

__device__ __forceinline__ void ldsm_x4(uint32_t* r, uint32_t addr) {
    asm volatile("ldmatrix.sync.aligned.m8n8.x4.shared.b16 {%0,%1,%2,%3}, [%4];"
        : "=r"(r[0]), "=r"(r[1]), "=r"(r[2]), "=r"(r[3]) : "r"(addr));
}
__device__ __forceinline__ void ldsm_x4_t(uint32_t* r, uint32_t addr) {
    asm volatile("ldmatrix.sync.aligned.m8n8.x4.trans.shared.b16 {%0,%1,%2,%3}, [%4];"
        : "=r"(r[0]), "=r"(r[1]), "=r"(r[2]), "=r"(r[3]) : "r"(addr));
}

__device__ __forceinline__ void cp16(uint32_t dst, const void* src, int sz) {
    asm volatile("cp.async.cg.shared.global [%0], [%1], 16, %2;"
        :: "r"(dst), "l"(src), "r"(sz));
}
__device__ __forceinline__ void cp_commit() {
    asm volatile("cp.async.commit_group;");
}
__device__ __forceinline__ void cp_wait0() {
    asm volatile("cp.async.wait_group 0;");
}

// ---------------------------------------------------------------------------
// Pre-convert kernels
// ---------------------------------------------------------------------------
__global__ void conv_split(const float* __restrict__ src,
                           uint32_t* __restrict__ h, uint32_t* __restrict__ l,
                           long long npairs)
{
    long long i = blockIdx.x * (long long)blockDim.x + threadIdx.x;
    long long stride = (long long)gridDim.x * blockDim.x;
    for (; i < npairs; i += stride) {
        float2 v = ((const float2*)src)[i];
        uint32_t hh, ll;
        split2(v.x, v.y, hh, ll);
        h[i] = hh; l[i] = ll;
    }
}

__global__ void transpose_split(const float* __restrict__ W,
                                __nv_bfloat16* __restrict__ Th,
                                __nv_bfloat16* __restrict__ Tl)
{
    __shared__ float ts[32][33];
    const int n0 = blockIdx.x * 32, k0 = blockIdx.y * 32;
    const int tx = threadIdx.x, ty = threadIdx.y;
#pragma unroll
    for (int i = 0; i < 4; i++)
        ts[ty + 8 * i][tx] = W[(long long)(k0 + ty + 8 * i) * 1024 + n0 + tx];
    __syncthreads();
#pragma unroll
    for (int i = 0; i < 4; i++) {
        float v = ts[tx][ty + 8 * i];
        __nv_bfloat16 h = __float2bfloat16(v);
        __nv_bfloat16 l = __float2bfloat16(v - __bfloat162float(h));
        long long o = (long long)(n0 + ty + 8 * i) * 1024 + k0 + tx;
        Th[o] = h; Tl[o] = l;
    }
}

// ---------------------------------------------------------------------------
// Pipelined GEMM: C[M,1024] = gatherA[M,1024] @ Wt^T (+bias)
// 128x128 tile, 8 warps, K chunk 32, 2-stage cp.async, ldmatrix frags.
// ---------------------------------------------------------------------------
#define KC    32
#define KPAD  40
#define STG_B (128 * KPAD * 2)          // 10240 bytes per array
#define GEMM_SMEM (2 * 4 * STG_B)       // 81920

__global__ __launch_bounds__(256) void gemm_bf16(
    const __nv_bfloat16* __restrict__ Ah, const __nv_bfloat16* __restrict__ Al,
    const __nv_bfloat16* __restrict__ Bh, const __nv_bfloat16* __restrict__ Bl,
    const float* __restrict__ bias, float* __restrict__ Cf,
    __nv_bfloat16* __restrict__ Ch, __nv_bfloat16* __restrict__ Cl,
    int M, int rpb, long long bstride, long long roff, int mode)
{
    extern __shared__ char dynsm[];
    const uint32_t sb = smem_u32(dynsm);

    const int tid  = threadIdx.x;
    const int wid  = tid >> 5;
    const int lane = tid & 31;
    const int gid  = lane >> 2;
    const int tig  = lane & 3;
    const int m0   = blockIdx.y * 128;
    const int n0   = blockIdx.x * 128;
    const int mb   = (wid & 3) * 32;
    const int nb   = (wid >> 2) * 64;

    // A staging: thread -> (row tid>>1, k-quarter (tid&1)*16)
    const int am  = tid >> 1;
    const int akq = (tid & 1) * 16;
    const __nv_bfloat16 *arh, *arl;
    int asz;
    {
        int gm = m0 + am;
        int ok = gm < M;
        int gmc = ok ? gm : 0;
        int bi = gmc / rpb;
        int t2 = gmc - bi * rpb;
        long long off = (long long)bi * bstride + roff + (long long)t2 * 1024 + akq;
        arh = Ah + off; arl = Al + off;
        asz = ok ? 16 : 0;
    }
    const int bn  = tid & 127;
    const int bkq = (tid >> 7) * 16;
    const __nv_bfloat16* brh = Bh + (long long)(n0 + bn) * 1024 + bkq;
    const __nv_bfloat16* brl = Bl + (long long)(n0 + bn) * 1024 + bkq;

    const uint32_t a_off = (uint32_t)(am * (KPAD * 2) + akq * 2);
    const uint32_t b_off = (uint32_t)(bn * (KPAD * 2) + bkq * 2);

    // fragment lane offsets (bf16 units)
    const int a_frag = (mb + (lane & 15)) * KPAD + (lane >> 4) * 8;
    const int b_frag = (nb + (lane >> 4) * 8 + (lane & 7)) * KPAD + ((lane >> 3) & 1) * 8;

    float acc[2][8][4];
#pragma unroll
    for (int mf = 0; mf < 2; mf++)
#pragma unroll
        for (int nf = 0; nf < 8; nf++)
#pragma unroll
            for (int j = 0; j < 4; j++) acc[mf][nf][j] = 0.f;

#define ISSUE(kc, stg) do {                                                  \
        const int k0_ = (kc) * KC;                                           \
        uint32_t bs_ = sb + (stg) * 4 * STG_B;                               \
        cp16(bs_ + a_off,                 arh + k0_,     asz);               \
        cp16(bs_ + a_off + 16,            arh + k0_ + 8, asz);               \
        cp16(bs_ + STG_B + a_off,         arl + k0_,     asz);               \
        cp16(bs_ + STG_B + a_off + 16,    arl + k0_ + 8, asz);               \
        cp16(bs_ + 2 * STG_B + b_off,     brh + k0_,     16);                \
        cp16(bs_ + 2 * STG_B + b_off + 16,brh + k0_ + 8, 16);                \
        cp16(bs_ + 3 * STG_B + b_off,     brl + k0_,     16);                \
        cp16(bs_ + 3 * STG_B + b_off + 16,brl + k0_ + 8, 16);                \
        cp_commit();                                                         \
    } while (0)

    ISSUE(0, 0);

    for (int kc = 0; kc < 32; kc++) {
        const int cur = kc & 1;
        cp_wait0();
        __syncthreads();
        if (kc + 1 < 32) ISSUE(kc + 1, cur ^ 1);

        const uint32_t aH = sb + cur * 4 * STG_B;
        const uint32_t aL = aH + STG_B;
        const uint32_t bH = aH + 2 * STG_B;
        const uint32_t bL = aH + 3 * STG_B;

#pragma unroll
        for (int ks = 0; ks < 2; ks++) {
            uint32_t fah[2][4], fal[2][4];
#pragma unroll
            for (int mf = 0; mf < 2; mf++) {
                uint32_t o = (uint32_t)(2 * (a_frag + mf * 16 * KPAD + ks * 16));
                ldsm_x4(fah[mf], aH + o);
                ldsm_x4(fal[mf], aL + o);
            }
#pragma unroll
            for (int nfp = 0; nfp < 4; nfp++) {
                uint32_t o = (uint32_t)(2 * (b_frag + nfp * 16 * KPAD + ks * 16));
                uint32_t bh4[4], bl4[4];
                ldsm_x4(bh4, bH + o);
                ldsm_x4(bl4, bL + o);
#pragma unroll
                for (int half = 0; half < 2; half++) {
                    int nf = nfp * 2 + half;
                    uint32_t* bhp = bh4 + half * 2;
                    uint32_t* blp = bl4 + half * 2;
#pragma unroll
                    for (int mf = 0; mf < 2; mf++) {
                        mma16816(acc[mf][nf], fah[mf], bhp);
                        mma16816(acc[mf][nf], fal[mf], bhp);
                        mma16816(acc[mf][nf], fah[mf], blp);
                    }
                }
            }
        }
        __syncthreads();
    }
#undef ISSUE

#pragma unroll
    for (int mf = 0; mf < 2; mf++) {
#pragma unroll
        for (int nf = 0; nf < 8; nf++) {
            int col = n0 + nb + nf * 8 + 2 * tig;
            int r0 = m0 + mb + mf * 16 + gid;
            int r1 = r0 + 8;
            if (mode == 1) {
                float b0 = bias[col], b1 = bias[col + 1];
                if (r0 < M)
                    *(float2*)(Cf + (long long)r0 * 1024 + col) =
                        make_float2(acc[mf][nf][0] + b0, acc[mf][nf][1] + b1);
                if (r1 < M)
                    *(float2*)(Cf + (long long)r1 * 1024 + col) =
                        make_float2(acc[mf][nf][2] + b0, acc[mf][nf][3] + b1);
            } else {
                uint32_t h, l;
                if (r0 < M) {
                    split2(acc[mf][nf][0], acc[mf][nf][1], h, l);
                    *(uint32_t*)(Ch + (long long)r0 * 1024 + col) = h;
                    *(uint32_t*)(Cl + (long long)r0 * 1024 + col) = l;
                }
                if (r1 < M) {
                    split2(acc[mf][nf][2], acc[mf][nf][3], h, l);
                    *(uint32_t*)(Ch + (long long)r1 * 1024 + col) = h;
                    *(uint32_t*)(Cl + (long long)r1 * 1024 + col) = l;
                }
            }
        }
    }
}

// ---------------------------------------------------------------------------
// Fused flash attention: CTA = 64 q rows x 1 head, 4 warps. Two phases
// (txt L=77, img L=256) with independent softmax; outputs summed in regs,
// written as bf16 hi/lo for the O-projection.
// ---------------------------------------------------------------------------
#define APAD 72
#define AQ_B (64 * APAD * 2)            // 9216 bytes per array
#define ATT_SMEM (6 * AQ_B)             // 55296

__global__ __launch_bounds__(128) void attn_fused(
    const __nv_bfloat16* __restrict__ Qh, const __nv_bfloat16* __restrict__ Ql,
    const __nv_bfloat16* __restrict__ K0h, const __nv_bfloat16* __restrict__ K0l,
    const __nv_bfloat16* __restrict__ V0h, const __nv_bfloat16* __restrict__ V0l,
    const __nv_bfloat16* __restrict__ K1h, const __nv_bfloat16* __restrict__ K1l,
    const __nv_bfloat16* __restrict__ V1h, const __nv_bfloat16* __restrict__ V1l,
    __nv_bfloat16* __restrict__ Ah, __nv_bfloat16* __restrict__ Al)
{
    extern __shared__ char dynsm[];
    const uint32_t sb = smem_u32(dynsm);
    const uint32_t sQH = sb, sQL = sb + AQ_B;
    const uint32_t sKH = sb + 2 * AQ_B, sKL = sb + 3 * AQ_B;
    const uint32_t sVH = sb + 4 * AQ_B, sVL = sb + 5 * AQ_B;

    const int tid  = threadIdx.x;
    const int wid  = tid >> 5;
    const int lane = tid & 31;
    const int gid  = lane >> 2;
    const int tig  = lane & 3;
    const int q0   = blockIdx.x * 64;
    const int h    = blockIdx.y;
    const int b    = blockIdx.z;
    const int wr   = wid * 16;

    const int sr = tid >> 1;               // staging row 0..63
    const int sc = (tid & 1) * 32;         // staging col half

    // ---- stage Q once
    {
        long long off = (long long)(b * N_ + q0 + sr) * INNER_ + h * DHEAD_ + sc;
        uint32_t d = (uint32_t)(sr * (APAD * 2) + sc * 2);
#pragma unroll
        for (int u = 0; u < 4; u++) {
            *(uint4*)(dynsm + d + 16 * u)        = *(const uint4*)(Qh + off + 8 * u);
            *(uint4*)(dynsm + AQ_B + d + 16 * u) = *(const uint4*)(Ql + off + 8 * u);
        }
    }
    __syncthreads();

    // ---- hoist Q fragments
    uint32_t qfh[4][4], qfl[4][4];
    {
        const int qf = (wr + (lane & 15)) * APAD + (lane >> 4) * 8;
#pragma unroll
        for (int kf = 0; kf < 4; kf++) {
            uint32_t o = (uint32_t)(2 * (qf + kf * 16));
            ldsm_x4(qfh[kf], sQH + o);
            ldsm_x4(qfl[kf], sQL + o);
        }
    }

    const int k_frag = ((lane >> 4) * 8 + (lane & 7)) * APAD + ((lane >> 3) & 1) * 8;
    const int v_frag = (((lane >> 3) & 1) * 8 + (lane & 7)) * APAD + (lane >> 4) * 8;

    float oout[8][4];
    const uint4 z4 = make_uint4(0, 0, 0, 0);

    for (int phase = 0; phase < 2; phase++) {
        const __nv_bfloat16* Kh_ = phase ? K1h : K0h;
        const __nv_bfloat16* Kl_ = phase ? K1l : K0l;
        const __nv_bfloat16* Vh_ = phase ? V1h : V0h;
        const __nv_bfloat16* Vl_ = phase ? V1l : V0l;
        const int L = phase ? IMG_ : TXT_;

        float acc[8][4];
#pragma unroll
        for (int nf = 0; nf < 8; nf++)
#pragma unroll
            for (int j = 0; j < 4; j++) acc[nf][j] = 0.f;
        float m0 = -1e30f, m1 = -1e30f, l0 = 0.f, l1 = 0.f;

        for (int c0 = 0; c0 < L; c0 += 64) {
            __syncthreads();
            {
                long long off = (long long)(b * L + c0 + sr) * INNER_ + h * DHEAD_ + sc;
                bool ok = (c0 + sr) < L;
                uint32_t d = (uint32_t)(sr * (APAD * 2) + sc * 2);
#pragma unroll
                for (int u = 0; u < 4; u++) {
                    uint4 kh = ok ? *(const uint4*)(Kh_ + off + 8 * u) : z4;
                    uint4 kl = ok ? *(const uint4*)(Kl_ + off + 8 * u) : z4;
                    uint4 vh = ok ? *(const uint4*)(Vh_ + off + 8 * u) : z4;
                    uint4 vl = ok ? *(const uint4*)(Vl_ + off + 8 * u) : z4;
                    *(uint4*)(dynsm + 2 * AQ_B + d + 16 * u) = kh;
                    *(uint4*)(dynsm + 3 * AQ_B + d + 16 * u) = kl;
                    *(uint4*)(dynsm + 4 * AQ_B + d + 16 * u) = vh;
                    *(uint4*)(dynsm + 5 * AQ_B + d + 16 * u) = vl;
                }
            }
            __syncthreads();

            // ---- S = Q K^T
            float s[8][4];
#pragma unroll
            for (int nf = 0; nf < 8; nf++)
#pragma unroll
                for (int j = 0; j < 4; j++) s[nf][j] = 0.f;
#pragma unroll
            for (int kf = 0; kf < 4; kf++) {
#pragma unroll
                for (int nfp = 0; nfp < 4; nfp++) {
                    uint32_t o = (uint32_t)(2 * (k_frag + nfp * 16 * APAD + kf * 16));
                    uint32_t kh4[4], kl4[4];
                    ldsm_x4(kh4, sKH + o);
                    ldsm_x4(kl4, sKL + o);
#pragma unroll
                    for (int half = 0; half < 2; half++) {
                        int nf = nfp * 2 + half;
                        mma16816(s[nf], qfh[kf], kh4 + half * 2);
                        mma16816(s[nf], qfl[kf], kh4 + half * 2);
                        mma16816(s[nf], qfh[kf], kl4 + half * 2);
                    }
                }
            }

            // ---- scale + mask
#pragma unroll
            for (int nf = 0; nf < 8; nf++) {
                int col = c0 + nf * 8 + 2 * tig;
                s[nf][0] *= SCALE_; s[nf][1] *= SCALE_;
                s[nf][2] *= SCALE_; s[nf][3] *= SCALE_;
                if (col >= L)     { s[nf][0] = -1e30f; s[nf][2] = -1e30f; }
                if (col + 1 >= L) { s[nf][1] = -1e30f; s[nf][3] = -1e30f; }
            }

            float mx0 = -1e30f, mx1 = -1e30f;
#pragma unroll
            for (int nf = 0; nf < 8; nf++) {
                mx0 = fmaxf(mx0, fmaxf(s[nf][0], s[nf][1]));
                mx1 = fmaxf(mx1, fmaxf(s[nf][2], s[nf][3]));
            }
            mx0 = fmaxf(mx0, __shfl_xor_sync(0xffffffff, mx0, 1));
            mx0 = fmaxf(mx0, __shfl_xor_sync(0xffffffff, mx0, 2));
            mx1 = fmaxf(mx1, __shfl_xor_sync(0xffffffff, mx1, 1));
            mx1 = fmaxf(mx1, __shfl_xor_sync(0xffffffff, mx1, 2));

            float nm0 = fmaxf(m0, mx0), nm1 = fmaxf(m1, mx1);
            float corr0 = __expf(m0 - nm0), corr1 = __expf(m1 - nm1);
            m0 = nm0; m1 = nm1;
#pragma unroll
            for (int nf = 0; nf < 8; nf++) {
                acc[nf][0] *= corr0; acc[nf][1] *= corr0;
                acc[nf][2] *= corr1; acc[nf][3] *= corr1;
            }

            uint32_t ph[8][2], pl[8][2];
            float sum0 = 0.f, sum1 = 0.f;
#pragma unroll
            for (int nf = 0; nf < 8; nf++) {
                float p0 = __expf(s[nf][0] - m0);
                float p1 = __expf(s[nf][1] - m0);
                float p2 = __expf(s[nf][2] - m1);
                float p3 = __expf(s[nf][3] - m1);
                sum0 += p0 + p1; sum1 += p2 + p3;
                split2(p0, p1, ph[nf][0], pl[nf][0]);
                split2(p2, p3, ph[nf][1], pl[nf][1]);
            }
            sum0 += __shfl_xor_sync(0xffffffff, sum0, 1);
            sum0 += __shfl_xor_sync(0xffffffff, sum0, 2);
            sum1 += __shfl_xor_sync(0xffffffff, sum1, 1);
            sum1 += __shfl_xor_sync(0xffffffff, sum1, 2);
            l0 = l0 * corr0 + sum0;
            l1 = l1 * corr1 + sum1;

            // ---- O += P V  (V via ldmatrix.trans)
#pragma unroll
            for (int kf = 0; kf < 4; kf++) {
                uint32_t pah[4] = { ph[2*kf][0], ph[2*kf][1], ph[2*kf+1][0], ph[2*kf+1][1] };
                uint32_t pal[4] = { pl[2*kf][0], pl[2*kf][1], pl[2*kf+1][0], pl[2*kf+1][1] };
#pragma unroll
                for (int dp = 0; dp < 4; dp++) {
                    uint32_t o = (uint32_t)(2 * (v_frag + kf * 16 * APAD + dp * 16));
                    uint32_t vh4[4], vl4[4];
                    ldsm_x4_t(vh4, sVH + o);
                    ldsm_x4_t(vl4, sVL + o);
#pragma unroll
                    for (int half = 0; half < 2; half++) {
                        int nfo = dp * 2 + half;
                        mma16816(acc[nfo], pah, vh4 + half * 2);
                        mma16816(acc[nfo], pal, vh4 + half * 2);
                        mma16816(acc[nfo], pah, vl4 + half * 2);
                    }
                }
            }
        }

        const float inv0 = 1.f / l0, inv1 = 1.f / l1;
        if (phase == 0) {
#pragma unroll
            for (int nf = 0; nf < 8; nf++) {
                oout[nf][0] = acc[nf][0] * inv0;
                oout[nf][1] = acc[nf][1] * inv0;
                oout[nf][2] = acc[nf][2] * inv1;
                oout[nf][3] = acc[nf][3] * inv1;
            }
        } else {
#pragma unroll
            for (int nf = 0; nf < 8; nf++) {
                oout[nf][0] += acc[nf][0] * inv0;
                oout[nf][1] += acc[nf][1] * inv0;
                oout[nf][2] += acc[nf][2] * inv1;
                oout[nf][3] += acc[nf][3] * inv1;
            }
        }
    }

    // ---- write bf16 hi/lo for O-projection
    const long long r0 = (long long)(b * N_ + q0 + wr + gid);
    const long long r1 = r0 + 8;
#pragma unroll
    for (int nf = 0; nf < 8; nf++) {
        int col = h * DHEAD_ + nf * 8 + 2 * tig;
        uint32_t hh, ll;
        split2(oout[nf][0], oout[nf][1], hh, ll);
        *(uint32_t*)(Ah + r0 * INNER_ + col) = hh;
        *(uint32_t*)(Al + r0 * INNER_ + col) = ll;
        split2(oout[nf][2], oout[nf][3], hh, ll);
        *(uint32_t*)(Ah + r1 * INNER_ + col) = hh;
        *(uint32_t*)(Al + r1 * INNER_ + col) = ll;
    }
}

// ---------------------------------------------------------------------------
extern "C" void kernel_launch(void* const* d_in, const int* in_sizes, int n_in,
                              void* d_out, int out_size)
{
    const float* x     = (const float*)d_in[0];
    const float* ctx   = (const float*)d_in[1];
    const float* Ws[6] = { (const float*)d_in[2], (const float*)d_in[3],
                           (const float*)d_in[4], (const float*)d_in[5],
                           (const float*)d_in[6], (const float*)d_in[7] };
    const float* bo    = (const float*)d_in[8];
    float* out = (float*)d_out;

    __nv_bfloat16 *xh, *xl, *ch, *cl, *Wth, *Wtl, *Qh, *Ql;
    __nv_bfloat16 *Kth, *Ktl, *Vth, *Vtl, *Kih, *Kil, *Vih, *Vil, *Ah, *Al;
    cudaGetSymbolAddress((void**)&xh, g_xh);   cudaGetSymbolAddress((void**)&xl, g_xl);
    cudaGetSymbolAddress((void**)&ch, g_ch);   cudaGetSymbolAddress((void**)&cl, g_cl);
    cudaGetSymbolAddress((void**)&Wth, g_Wth); cudaGetSymbolAddress((void**)&Wtl, g_Wtl);
    cudaGetSymbolAddress((void**)&Qh, g_Qh);   cudaGetSymbolAddress((void**)&Ql, g_Ql);
    cudaGetSymbolAddress((void**)&Kth, g_Kth); cudaGetSymbolAddress((void**)&Ktl, g_Ktl);
    cudaGetSymbolAddress((void**)&Vth, g_Vth); cudaGetSymbolAddress((void**)&Vtl, g_Vtl);
    cudaGetSymbolAddress((void**)&Kih, g_Kih); cudaGetSymbolAddress((void**)&Kil, g_Kil);
    cudaGetSymbolAddress((void**)&Vih, g_Vih); cudaGetSymbolAddress((void**)&Vil, g_Vil);
    cudaGetSymbolAddress((void**)&Ah, g_Ah);   cudaGetSymbolAddress((void**)&Al, g_Al);

    cudaFuncSetAttribute(gemm_bf16, cudaFuncAttributeMaxDynamicSharedMemorySize,
                         GEMM_SMEM);
    cudaFuncSetAttribute(attn_fused, cudaFuncAttributeMaxDynamicSharedMemorySize,
                         ATT_SMEM);

    const int M_q   = B_ * N_;
    const int M_txt = B_ * TXT_;
    const int M_img = B_ * IMG_;

    conv_split<<<2048, 256>>>(x,   (uint32_t*)xh, (uint32_t*)xl, NX / 2);
    conv_split<<<1024, 256>>>(ctx, (uint32_t*)ch, (uint32_t*)cl, NCTX / 2);
    for (int w = 0; w < 6; w++)
        transpose_split<<<dim3(32, 32), dim3(32, 8)>>>(
            Ws[w], Wth + (long long)w * 1048576, Wtl + (long long)w * 1048576);

    gemm_bf16<<<dim3(8, 256), 256, GEMM_SMEM>>>(xh, xl, Wth, Wtl, nullptr, nullptr,
        Qh, Ql, M_q, N_, (long long)N_ * 1024, 0, 0);
    gemm_bf16<<<dim3(8, 10), 256, GEMM_SMEM>>>(ch, cl, Wth + 1048576, Wtl + 1048576,
        nullptr, nullptr, Kth, Ktl, M_txt, TXT_, (long long)CTXL_ * 1024, 0, 0);
    gemm_bf16<<<dim3(8, 10), 256, GEMM_SMEM>>>(ch, cl, Wth + 2 * 1048576, Wtl + 2 * 1048576,
        nullptr, nullptr, Vth, Vtl, M_txt, TXT_, (long long)CTXL_ * 1024, 0, 0);
    gemm_bf16<<<dim3(8, 32), 256, GEMM_SMEM>>>(ch, cl, Wth + 3 * 1048576, Wtl + 3 * 1048576,
        nullptr, nullptr, Kih, Kil, M_img, IMG_, (long long)CTXL_ * 1024,
        (long long)TXT_ * 1024, 0);
    gemm_bf16<<<dim3(8, 32), 256, GEMM_SMEM>>>(ch, cl, Wth + 4 * 1048576, Wtl + 4 * 1048576,
        nullptr, nullptr, Vih, Vil, M_img, IMG_, (long long)CTXL_ * 1024,
        (long long)TXT_ * 1024, 0);

    attn_fused<<<dim3(N_ / 64, HEADS_, B_), 128, ATT_SMEM>>>(
        Qh, Ql, Kth, Ktl, Vth, Vtl, Kih, Kil, Vih, Vil, Ah, Al);

    gemm_bf16<<<dim3(8, 256), 256, GEMM_SMEM>>>(Ah, Al, Wth + 5 * 1048576, Wtl + 5 * 1048576,
        bo, out, nullptr, nullptr, M_q, M_q, 0, 0, 1);
}

// round 10
// speedup vs baseline: 2.2434x; 1.1103x over previous
#include <cuda_runtime.h>
#include <cuda_bf16.h>
#include <math.h>
#include <stdint.h>

// ---------------------------------------------------------------------------
// CrossAttention: bf16x3-split mma.sync GEMMs (cp.async + ldmatrix, 1-sync
// pipeline) + fused two-phase flash attention (128-row CTAs, cp.async KV).
// ---------------------------------------------------------------------------

#define B_      16
#define N_      2048
#define HEADS_  16
#define DHEAD_  64
#define INNER_  1024
#define CTXL_   333
#define TXT_    77
#define IMG_    256
#define SCALE_  0.125f

#define NX      (33554432LL)
#define NCTX    (16LL * 333 * 1024)

__device__ __nv_bfloat16 g_xh[NX],  g_xl[NX];
__device__ __nv_bfloat16 g_ch[NCTX], g_cl[NCTX];
__device__ __nv_bfloat16 g_Wth[6 * 1048576], g_Wtl[6 * 1048576];
__device__ __nv_bfloat16 g_Qh[NX],  g_Ql[NX];
__device__ __nv_bfloat16 g_Kth[1261568], g_Ktl[1261568];
__device__ __nv_bfloat16 g_Vth[1261568], g_Vtl[1261568];
__device__ __nv_bfloat16 g_Kih[4194304], g_Kil[4194304];
__device__ __nv_bfloat16 g_Vih[4194304], g_Vil[4194304];
__device__ __nv_bfloat16 g_Ah[NX],  g_Al[NX];

// ---------------------------------------------------------------------------
__device__ __forceinline__ uint32_t smem_u32(const void* p) {
    uint32_t a;
    asm("{ .reg .u64 t; cvta.to.shared.u64 t, %1; cvt.u32.u64 %0, t; }"
        : "=r"(a) : "l"(p));
    return a;
}

__device__ __forceinline__ void split2(float x, float y, uint32_t& h, uint32_t& l) {
    __nv_bfloat16 hx = __float2bfloat16(x);
    __nv_bfloat16 hy = __float2bfloat16(y);
    __nv_bfloat16 lx = __float2bfloat16(x - __bfloat162float(hx));
    __nv_bfloat16 ly = __float2bfloat16(y - __bfloat162float(hy));
    h = (uint32_t)__bfloat16_as_ushort(hx) | ((uint32_t)__bfloat16_as_ushort(hy) << 16);
    l = (uint32_t)__bfloat16_as_ushort(lx) | ((uint32_t)__bfloat16_as_ushort(ly) << 16);
}

__device__ __forceinline__ void mma16816(float* c, const uint32_t* a, const uint32_t* b) {
    asm volatile(
        "mma.sync.aligned.m16n8k16.row.col.f32.bf16.bf16.f32 "
        "{%0,%1,%2,%3}, {%4,%5,%6,%7}, {%8,%9}, {%0,%1,%2,%3};"
        : "+f"(c[0]), "+f"(c[1]), "+f"(c[2]), "+f"(c[3])
        : "r"(a[0]), "r"(a[1]), "r"(a[2]), "r"(a[3]), "r"(b[0]), "r"(b[1]));
}

__device__ __forceinline__ void ldsm_x4(uint32_t* r, uint32_t addr) {
    asm volatile("ldmatrix.sync.aligned.m8n8.x4.shared.b16 {%0,%1,%2,%3}, [%4];"
        : "=r"(r[0]), "=r"(r[1]), "=r"(r[2]), "=r"(r[3]) : "r"(addr));
}
__device__ __forceinline__ void ldsm_x4_t(uint32_t* r, uint32_t addr) {
    asm volatile("ldmatrix.sync.aligned.m8n8.x4.trans.shared.b16 {%0,%1,%2,%3}, [%4];"
        : "=r"(r[0]), "=r"(r[1]), "=r"(r[2]), "=r"(r[3]) : "r"(addr));
}

__device__ __forceinline__ void cp16(uint32_t dst, const void* src, int sz) {
    asm volatile("cp.async.cg.shared.global [%0], [%1], 16, %2;"
        :: "r"(dst), "l"(src), "r"(sz));
}
__device__ __forceinline__ void cp_commit() {
    asm volatile("cp.async.commit_group;");
}
__device__ __forceinline__ void cp_wait0() {
    asm volatile("cp.async.wait_group 0;");
}

// ---------------------------------------------------------------------------
// Pre-convert kernels
// ---------------------------------------------------------------------------
__global__ void conv_split(const float* __restrict__ src,
                           uint32_t* __restrict__ h, uint32_t* __restrict__ l,
                           long long npairs)
{
    long long i = blockIdx.x * (long long)blockDim.x + threadIdx.x;
    long long stride = (long long)gridDim.x * blockDim.x;
    for (; i < npairs; i += stride) {
        float2 v = ((const float2*)src)[i];
        uint32_t hh, ll;
        split2(v.x, v.y, hh, ll);
        h[i] = hh; l[i] = ll;
    }
}

__global__ void transpose_split(const float* __restrict__ W,
                                __nv_bfloat16* __restrict__ Th,
                                __nv_bfloat16* __restrict__ Tl)
{
    __shared__ float ts[32][33];
    const int n0 = blockIdx.x * 32, k0 = blockIdx.y * 32;
    const int tx = threadIdx.x, ty = threadIdx.y;
#pragma unroll
    for (int i = 0; i < 4; i++)
        ts[ty + 8 * i][tx] = W[(long long)(k0 + ty + 8 * i) * 1024 + n0 + tx];
    __syncthreads();
#pragma unroll
    for (int i = 0; i < 4; i++) {
        float v = ts[tx][ty + 8 * i];
        __nv_bfloat16 h = __float2bfloat16(v);
        __nv_bfloat16 l = __float2bfloat16(v - __bfloat162float(h));
        long long o = (long long)(n0 + ty + 8 * i) * 1024 + k0 + tx;
        Th[o] = h; Tl[o] = l;
    }
}

// ---------------------------------------------------------------------------
// Pipelined GEMM: 128x128 tile, 8 warps, K chunk 32, 2-stage cp.async,
// ldmatrix frags, ONE __syncthreads per K-chunk.
// ---------------------------------------------------------------------------
#define KC    32
#define KPAD  40
#define STG_B (128 * KPAD * 2)
#define GEMM_SMEM (2 * 4 * STG_B)

__global__ __launch_bounds__(256) void gemm_bf16(
    const __nv_bfloat16* __restrict__ Ah, const __nv_bfloat16* __restrict__ Al,
    const __nv_bfloat16* __restrict__ Bh, const __nv_bfloat16* __restrict__ Bl,
    const float* __restrict__ bias, float* __restrict__ Cf,
    __nv_bfloat16* __restrict__ Ch, __nv_bfloat16* __restrict__ Cl,
    int M, int rpb, long long bstride, long long roff, int mode)
{
    extern __shared__ char dynsm[];
    const uint32_t sb = smem_u32(dynsm);

    const int tid  = threadIdx.x;
    const int wid  = tid >> 5;
    const int lane = tid & 31;
    const int gid  = lane >> 2;
    const int tig  = lane & 3;
    const int m0   = blockIdx.y * 128;
    const int n0   = blockIdx.x * 128;
    const int mb   = (wid & 3) * 32;
    const int nb   = (wid >> 2) * 64;

    const int am  = tid >> 1;
    const int akq = (tid & 1) * 16;
    const __nv_bfloat16 *arh, *arl;
    int asz;
    {
        int gm = m0 + am;
        int ok = gm < M;
        int gmc = ok ? gm : 0;
        int bi = gmc / rpb;
        int t2 = gmc - bi * rpb;
        long long off = (long long)bi * bstride + roff + (long long)t2 * 1024 + akq;
        arh = Ah + off; arl = Al + off;
        asz = ok ? 16 : 0;
    }
    const int bn  = tid & 127;
    const int bkq = (tid >> 7) * 16;
    const __nv_bfloat16* brh = Bh + (long long)(n0 + bn) * 1024 + bkq;
    const __nv_bfloat16* brl = Bl + (long long)(n0 + bn) * 1024 + bkq;

    const uint32_t a_off = (uint32_t)(am * (KPAD * 2) + akq * 2);
    const uint32_t b_off = (uint32_t)(bn * (KPAD * 2) + bkq * 2);

    const int a_frag = (mb + (lane & 15)) * KPAD + (lane >> 4) * 8;
    const int b_frag = (nb + (lane >> 4) * 8 + (lane & 7)) * KPAD + ((lane >> 3) & 1) * 8;

    float acc[2][8][4];
#pragma unroll
    for (int mf = 0; mf < 2; mf++)
#pragma unroll
        for (int nf = 0; nf < 8; nf++)
#pragma unroll
            for (int j = 0; j < 4; j++) acc[mf][nf][j] = 0.f;

#define ISSUE(kc, stg) do {                                                  \
        const int k0_ = (kc) * KC;                                           \
        uint32_t bs_ = sb + (stg) * 4 * STG_B;                               \
        cp16(bs_ + a_off,                 arh + k0_,     asz);               \
        cp16(bs_ + a_off + 16,            arh + k0_ + 8, asz);               \
        cp16(bs_ + STG_B + a_off,         arl + k0_,     asz);               \
        cp16(bs_ + STG_B + a_off + 16,    arl + k0_ + 8, asz);               \
        cp16(bs_ + 2 * STG_B + b_off,     brh + k0_,     16);                \
        cp16(bs_ + 2 * STG_B + b_off + 16,brh + k0_ + 8, 16);                \
        cp16(bs_ + 3 * STG_B + b_off,     brl + k0_,     16);                \
        cp16(bs_ + 3 * STG_B + b_off + 16,brl + k0_ + 8, 16);                \
        cp_commit();                                                         \
    } while (0)

    ISSUE(0, 0);

    for (int kc = 0; kc < 32; kc++) {
        const int cur = kc & 1;
        cp_wait0();
        __syncthreads();
        if (kc + 1 < 32) ISSUE(kc + 1, cur ^ 1);

        const uint32_t aH = sb + cur * 4 * STG_B;
        const uint32_t aL = aH + STG_B;
        const uint32_t bH = aH + 2 * STG_B;
        const uint32_t bL = aH + 3 * STG_B;

#pragma unroll
        for (int ks = 0; ks < 2; ks++) {
            uint32_t fah[2][4], fal[2][4];
#pragma unroll
            for (int mf = 0; mf < 2; mf++) {
                uint32_t o = (uint32_t)(2 * (a_frag + mf * 16 * KPAD + ks * 16));
                ldsm_x4(fah[mf], aH + o);
                ldsm_x4(fal[mf], aL + o);
            }
#pragma unroll
            for (int nfp = 0; nfp < 4; nfp++) {
                uint32_t o = (uint32_t)(2 * (b_frag + nfp * 16 * KPAD + ks * 16));
                uint32_t bh4[4], bl4[4];
                ldsm_x4(bh4, bH + o);
                ldsm_x4(bl4, bL + o);
#pragma unroll
                for (int half = 0; half < 2; half++) {
                    int nf = nfp * 2 + half;
                    uint32_t* bhp = bh4 + half * 2;
                    uint32_t* blp = bl4 + half * 2;
#pragma unroll
                    for (int mf = 0; mf < 2; mf++) {
                        mma16816(acc[mf][nf], fah[mf], bhp);
                        mma16816(acc[mf][nf], fal[mf], bhp);
                        mma16816(acc[mf][nf], fah[mf], blp);
                    }
                }
            }
        }
        // no trailing sync: next iteration's wait+sync protects buffer reuse
    }
#undef ISSUE

#pragma unroll
    for (int mf = 0; mf < 2; mf++) {
#pragma unroll
        for (int nf = 0; nf < 8; nf++) {
            int col = n0 + nb + nf * 8 + 2 * tig;
            int r0 = m0 + mb + mf * 16 + gid;
            int r1 = r0 + 8;
            if (mode == 1) {
                float b0 = bias[col], b1 = bias[col + 1];
                if (r0 < M)
                    *(float2*)(Cf + (long long)r0 * 1024 + col) =
                        make_float2(acc[mf][nf][0] + b0, acc[mf][nf][1] + b1);
                if (r1 < M)
                    *(float2*)(Cf + (long long)r1 * 1024 + col) =
                        make_float2(acc[mf][nf][2] + b0, acc[mf][nf][3] + b1);
            } else {
                uint32_t h, l;
                if (r0 < M) {
                    split2(acc[mf][nf][0], acc[mf][nf][1], h, l);
                    *(uint32_t*)(Ch + (long long)r0 * 1024 + col) = h;
                    *(uint32_t*)(Cl + (long long)r0 * 1024 + col) = l;
                }
                if (r1 < M) {
                    split2(acc[mf][nf][2], acc[mf][nf][3], h, l);
                    *(uint32_t*)(Ch + (long long)r1 * 1024 + col) = h;
                    *(uint32_t*)(Cl + (long long)r1 * 1024 + col) = l;
                }
            }
        }
    }
}

// ---------------------------------------------------------------------------
// Fused flash attention: CTA = 128 q rows x 1 head, 8 warps.
// KV chunks of 64 double-buffered via cp.async; chunk sequence linearized
// across txt (2 chunks) + img (4 chunks) phases; single sync per chunk.
// ---------------------------------------------------------------------------
#define APAD  72
#define QS_B  (128 * APAD * 2)          // 18432 per Q array
#define KVS_B (64 * APAD * 2)           // 9216 per KV array
#define KV_STG (4 * KVS_B)              // 36864 per stage
#define ATT_SMEM (2 * QS_B + 2 * KV_STG) // 110592

__global__ __launch_bounds__(256) void attn_fused(
    const __nv_bfloat16* __restrict__ Qh, const __nv_bfloat16* __restrict__ Ql,
    const __nv_bfloat16* __restrict__ K0h, const __nv_bfloat16* __restrict__ K0l,
    const __nv_bfloat16* __restrict__ V0h, const __nv_bfloat16* __restrict__ V0l,
    const __nv_bfloat16* __restrict__ K1h, const __nv_bfloat16* __restrict__ K1l,
    const __nv_bfloat16* __restrict__ V1h, const __nv_bfloat16* __restrict__ V1l,
    __nv_bfloat16* __restrict__ Ah, __nv_bfloat16* __restrict__ Al)
{
    extern __shared__ char dynsm[];
    const uint32_t sb = smem_u32(dynsm);
    const uint32_t sQH = sb, sQL = sb + QS_B;
    const uint32_t kvbase = sb + 2 * QS_B;

    const int tid  = threadIdx.x;
    const int wid  = tid >> 5;          // 0..7
    const int lane = tid & 31;
    const int gid  = lane >> 2;
    const int tig  = lane & 3;
    const int q0   = blockIdx.x * 128;
    const int h    = blockIdx.y;
    const int b    = blockIdx.z;
    const int wr   = wid * 16;

    const __nv_bfloat16* KH[2] = { K0h, K1h };
    const __nv_bfloat16* KL[2] = { K0l, K1l };
    const __nv_bfloat16* VH[2] = { V0h, V1h };
    const __nv_bfloat16* VL[2] = { V0l, V1l };
    const int LP[2] = { TXT_, IMG_ };

    // ---- stage Q (256 threads cover 128 rows x 2 col-halves)
    {
        int r = tid >> 1, sc = (tid & 1) * 32;
        long long off = (long long)(b * N_ + q0 + r) * INNER_ + h * DHEAD_ + sc;
        uint32_t d = (uint32_t)(r * (APAD * 2) + sc * 2);
#pragma unroll
        for (int u = 0; u < 4; u++) {
            *(uint4*)(dynsm + d + 16 * u)        = *(const uint4*)(Qh + off + 8 * u);
            *(uint4*)(dynsm + QS_B + d + 16 * u) = *(const uint4*)(Ql + off + 8 * u);
        }
    }

    // ---- KV staging mapping: 256 threads, 64 rows x 4 col-quarters
    const int sr = tid >> 2;
    const int sq = (tid & 3) * 16;
    const uint32_t kvd = (uint32_t)(sr * (APAD * 2) + sq * 2);

#define AISSUE(ci) do {                                                       \
        int ph_ = (ci) >= 2;                                                  \
        int c0_ = ph_ ? ((ci) - 2) * 64 : (ci) * 64;                          \
        int L_  = LP[ph_];                                                    \
        int row_ = c0_ + sr;                                                  \
        int ok_  = row_ < L_;                                                 \
        long long off_ = (long long)(b * L_ + (ok_ ? row_ : 0)) * INNER_      \
                         + h * DHEAD_ + sq;                                   \
        int sz_ = ok_ ? 16 : 0;                                               \
        uint32_t bs_ = kvbase + ((ci) & 1) * KV_STG + kvd;                    \
        cp16(bs_,                 KH[ph_] + off_,     sz_);                   \
        cp16(bs_ + 16,            KH[ph_] + off_ + 8, sz_);                   \
        cp16(bs_ + KVS_B,         KL[ph_] + off_,     sz_);                   \
        cp16(bs_ + KVS_B + 16,    KL[ph_] + off_ + 8, sz_);                   \
        cp16(bs_ + 2 * KVS_B,     VH[ph_] + off_,     sz_);                   \
        cp16(bs_ + 2 * KVS_B + 16,VH[ph_] + off_ + 8, sz_);                   \
        cp16(bs_ + 3 * KVS_B,     VL[ph_] + off_,     sz_);                   \
        cp16(bs_ + 3 * KVS_B + 16,VL[ph_] + off_ + 8, sz_);                   \
        cp_commit();                                                          \
    } while (0)

    AISSUE(0);
    __syncthreads();   // Q visible

    // ---- hoist Q fragments
    uint32_t qfh[4][4], qfl[4][4];
    {
        const int qf = (wr + (lane & 15)) * APAD + (lane >> 4) * 8;
#pragma unroll
        for (int kf = 0; kf < 4; kf++) {
            uint32_t o = (uint32_t)(2 * (qf + kf * 16));
            ldsm_x4(qfh[kf], sQH + o);
            ldsm_x4(qfl[kf], sQL + o);
        }
    }

    const int k_frag = ((lane >> 4) * 8 + (lane & 7)) * APAD + ((lane >> 3) & 1) * 8;
    const int v_frag = (((lane >> 3) & 1) * 8 + (lane & 7)) * APAD + (lane >> 4) * 8;

    float acc[8][4];
#pragma unroll
    for (int nf = 0; nf < 8; nf++)
#pragma unroll
        for (int j = 0; j < 4; j++) acc[nf][j] = 0.f;
    float m0 = -1e30f, m1 = -1e30f, l0 = 0.f, l1 = 0.f;
    float oout[8][4];

    for (int ci = 0; ci < 6; ci++) {
        cp_wait0();
        __syncthreads();
        if (ci + 1 < 6) AISSUE(ci + 1);

        if (ci == 2) {   // phase boundary: finalize txt, reset state
            float inv0 = 1.f / l0, inv1 = 1.f / l1;
#pragma unroll
            for (int nf = 0; nf < 8; nf++) {
                oout[nf][0] = acc[nf][0] * inv0;
                oout[nf][1] = acc[nf][1] * inv0;
                oout[nf][2] = acc[nf][2] * inv1;
                oout[nf][3] = acc[nf][3] * inv1;
                acc[nf][0] = acc[nf][1] = acc[nf][2] = acc[nf][3] = 0.f;
            }
            m0 = m1 = -1e30f; l0 = l1 = 0.f;
        }

        const int ph_ = ci >= 2;
        const int c0 = ph_ ? (ci - 2) * 64 : ci * 64;
        const int L  = LP[ph_];
        const uint32_t stg = kvbase + (ci & 1) * KV_STG;
        const uint32_t sKH = stg, sKL = stg + KVS_B;
        const uint32_t sVH = stg + 2 * KVS_B, sVL = stg + 3 * KVS_B;

        // ---- S = Q K^T
        float s[8][4];
#pragma unroll
        for (int nf = 0; nf < 8; nf++)
#pragma unroll
            for (int j = 0; j < 4; j++) s[nf][j] = 0.f;
#pragma unroll
        for (int kf = 0; kf < 4; kf++) {
#pragma unroll
            for (int nfp = 0; nfp < 4; nfp++) {
                uint32_t o = (uint32_t)(2 * (k_frag + nfp * 16 * APAD + kf * 16));
                uint32_t kh4[4], kl4[4];
                ldsm_x4(kh4, sKH + o);
                ldsm_x4(kl4, sKL + o);
#pragma unroll
                for (int half = 0; half < 2; half++) {
                    int nf = nfp * 2 + half;
                    mma16816(s[nf], qfh[kf], kh4 + half * 2);
                    mma16816(s[nf], qfl[kf], kh4 + half * 2);
                    mma16816(s[nf], qfh[kf], kl4 + half * 2);
                }
            }
        }

#pragma unroll
        for (int nf = 0; nf < 8; nf++) {
            int col = c0 + nf * 8 + 2 * tig;
            s[nf][0] *= SCALE_; s[nf][1] *= SCALE_;
            s[nf][2] *= SCALE_; s[nf][3] *= SCALE_;
            if (col >= L)     { s[nf][0] = -1e30f; s[nf][2] = -1e30f; }
            if (col + 1 >= L) { s[nf][1] = -1e30f; s[nf][3] = -1e30f; }
        }

        float mx0 = -1e30f, mx1 = -1e30f;
#pragma unroll
        for (int nf = 0; nf < 8; nf++) {
            mx0 = fmaxf(mx0, fmaxf(s[nf][0], s[nf][1]));
            mx1 = fmaxf(mx1, fmaxf(s[nf][2], s[nf][3]));
        }
        mx0 = fmaxf(mx0, __shfl_xor_sync(0xffffffff, mx0, 1));
        mx0 = fmaxf(mx0, __shfl_xor_sync(0xffffffff, mx0, 2));
        mx1 = fmaxf(mx1, __shfl_xor_sync(0xffffffff, mx1, 1));
        mx1 = fmaxf(mx1, __shfl_xor_sync(0xffffffff, mx1, 2));

        float nm0 = fmaxf(m0, mx0), nm1 = fmaxf(m1, mx1);
        float corr0 = __expf(m0 - nm0), corr1 = __expf(m1 - nm1);
        m0 = nm0; m1 = nm1;
#pragma unroll
        for (int nf = 0; nf < 8; nf++) {
            acc[nf][0] *= corr0; acc[nf][1] *= corr0;
            acc[nf][2] *= corr1; acc[nf][3] *= corr1;
        }

        uint32_t ph[8][2], pl[8][2];
        float sum0 = 0.f, sum1 = 0.f;
#pragma unroll
        for (int nf = 0; nf < 8; nf++) {
            float p0 = __expf(s[nf][0] - m0);
            float p1 = __expf(s[nf][1] - m0);
            float p2 = __expf(s[nf][2] - m1);
            float p3 = __expf(s[nf][3] - m1);
            sum0 += p0 + p1; sum1 += p2 + p3;
            split2(p0, p1, ph[nf][0], pl[nf][0]);
            split2(p2, p3, ph[nf][1], pl[nf][1]);
        }
        sum0 += __shfl_xor_sync(0xffffffff, sum0, 1);
        sum0 += __shfl_xor_sync(0xffffffff, sum0, 2);
        sum1 += __shfl_xor_sync(0xffffffff, sum1, 1);
        sum1 += __shfl_xor_sync(0xffffffff, sum1, 2);
        l0 = l0 * corr0 + sum0;
        l1 = l1 * corr1 + sum1;

        // ---- O += P V  (V via ldmatrix.trans)
#pragma unroll
        for (int kf = 0; kf < 4; kf++) {
            uint32_t pah[4] = { ph[2*kf][0], ph[2*kf][1], ph[2*kf+1][0], ph[2*kf+1][1] };
            uint32_t pal[4] = { pl[2*kf][0], pl[2*kf][1], pl[2*kf+1][0], pl[2*kf+1][1] };
#pragma unroll
            for (int dp = 0; dp < 4; dp++) {
                uint32_t o = (uint32_t)(2 * (v_frag + kf * 16 * APAD + dp * 16));
                uint32_t vh4[4], vl4[4];
                ldsm_x4_t(vh4, sVH + o);
                ldsm_x4_t(vl4, sVL + o);
#pragma unroll
                for (int half = 0; half < 2; half++) {
                    int nfo = dp * 2 + half;
                    mma16816(acc[nfo], pah, vh4 + half * 2);
                    mma16816(acc[nfo], pal, vh4 + half * 2);
                    mma16816(acc[nfo], pah, vl4 + half * 2);
                }
            }
        }
    }
#undef AISSUE

    // ---- finalize img phase, write bf16 hi/lo
    const float inv0 = 1.f / l0, inv1 = 1.f / l1;
    const long long r0 = (long long)(b * N_ + q0 + wr + gid);
    const long long r1 = r0 + 8;
#pragma unroll
    for (int nf = 0; nf < 8; nf++) {
        int col = h * DHEAD_ + nf * 8 + 2 * tig;
        uint32_t hh, ll;
        split2(oout[nf][0] + acc[nf][0] * inv0, oout[nf][1] + acc[nf][1] * inv0, hh, ll);
        *(uint32_t*)(Ah + r0 * INNER_ + col) = hh;
        *(uint32_t*)(Al + r0 * INNER_ + col) = ll;
        split2(oout[nf][2] + acc[nf][2] * inv1, oout[nf][3] + acc[nf][3] * inv1, hh, ll);
        *(uint32_t*)(Ah + r1 * INNER_ + col) = hh;
        *(uint32_t*)(Al + r1 * INNER_ + col) = ll;
    }
}

// ---------------------------------------------------------------------------
extern "C" void kernel_launch(void* const* d_in, const int* in_sizes, int n_in,
                              void* d_out, int out_size)
{
    const float* x     = (const float*)d_in[0];
    const float* ctx   = (const float*)d_in[1];
    const float* Ws[6] = { (const float*)d_in[2], (const float*)d_in[3],
                           (const float*)d_in[4], (const float*)d_in[5],
                           (const float*)d_in[6], (const float*)d_in[7] };
    const float* bo    = (const float*)d_in[8];
    float* out = (float*)d_out;

    __nv_bfloat16 *xh, *xl, *ch, *cl, *Wth, *Wtl, *Qh, *Ql;
    __nv_bfloat16 *Kth, *Ktl, *Vth, *Vtl, *Kih, *Kil, *Vih, *Vil, *Ah, *Al;
    cudaGetSymbolAddress((void**)&xh, g_xh);   cudaGetSymbolAddress((void**)&xl, g_xl);
    cudaGetSymbolAddress((void**)&ch, g_ch);   cudaGetSymbolAddress((void**)&cl, g_cl);
    cudaGetSymbolAddress((void**)&Wth, g_Wth); cudaGetSymbolAddress((void**)&Wtl, g_Wtl);
    cudaGetSymbolAddress((void**)&Qh, g_Qh);   cudaGetSymbolAddress((void**)&Ql, g_Ql);
    cudaGetSymbolAddress((void**)&Kth, g_Kth); cudaGetSymbolAddress((void**)&Ktl, g_Ktl);
    cudaGetSymbolAddress((void**)&Vth, g_Vth); cudaGetSymbolAddress((void**)&Vtl, g_Vtl);
    cudaGetSymbolAddress((void**)&Kih, g_Kih); cudaGetSymbolAddress((void**)&Kil, g_Kil);
    cudaGetSymbolAddress((void**)&Vih, g_Vih); cudaGetSymbolAddress((void**)&Vil, g_Vil);
    cudaGetSymbolAddress((void**)&Ah, g_Ah);   cudaGetSymbolAddress((void**)&Al, g_Al);

    cudaFuncSetAttribute(gemm_bf16, cudaFuncAttributeMaxDynamicSharedMemorySize,
                         GEMM_SMEM);
    cudaFuncSetAttribute(attn_fused, cudaFuncAttributeMaxDynamicSharedMemorySize,
                         ATT_SMEM);

    const int M_q   = B_ * N_;
    const int M_txt = B_ * TXT_;
    const int M_img = B_ * IMG_;

    conv_split<<<2048, 256>>>(x,   (uint32_t*)xh, (uint32_t*)xl, NX / 2);
    conv_split<<<1024, 256>>>(ctx, (uint32_t*)ch, (uint32_t*)cl, NCTX / 2);
    for (int w = 0; w < 6; w++)
        transpose_split<<<dim3(32, 32), dim3(32, 8)>>>(
            Ws[w], Wth + (long long)w * 1048576, Wtl + (long long)w * 1048576);

    gemm_bf16<<<dim3(8, 256), 256, GEMM_SMEM>>>(xh, xl, Wth, Wtl, nullptr, nullptr,
        Qh, Ql, M_q, N_, (long long)N_ * 1024, 0, 0);
    gemm_bf16<<<dim3(8, 10), 256, GEMM_SMEM>>>(ch, cl, Wth + 1048576, Wtl + 1048576,
        nullptr, nullptr, Kth, Ktl, M_txt, TXT_, (long long)CTXL_ * 1024, 0, 0);
    gemm_bf16<<<dim3(8, 10), 256, GEMM_SMEM>>>(ch, cl, Wth + 2 * 1048576, Wtl + 2 * 1048576,
        nullptr, nullptr, Vth, Vtl, M_txt, TXT_, (long long)CTXL_ * 1024, 0, 0);
    gemm_bf16<<<dim3(8, 32), 256, GEMM_SMEM>>>(ch, cl, Wth + 3 * 1048576, Wtl + 3 * 1048576,
        nullptr, nullptr, Kih, Kil, M_img, IMG_, (long long)CTXL_ * 1024,
        (long long)TXT_ * 1024, 0);
    gemm_bf16<<<dim3(8, 32), 256, GEMM_SMEM>>>(ch, cl, Wth + 4 * 1048576, Wtl + 4 * 1048576,
        nullptr, nullptr, Vih, Vil, M_img, IMG_, (long long)CTXL_ * 1024,
        (long long)TXT_ * 1024, 0);

    attn_fused<<<dim3(N_ / 128, HEADS_, B_), 256, ATT_SMEM>>>(
        Qh, Ql, Kth, Ktl, Vth, Vtl, Kih, Kil, Vih, Vil, Ah, Al);

    gemm_bf16<<<dim3(8, 256), 256, GEMM_SMEM>>>(Ah, Al, Wth + 5 * 1048576, Wtl + 5 * 1048576,
        bo, out, nullptr, nullptr, M_q, M_q, 0, 0, 1);
}